// round 5
// baseline (speedup 1.0000x reference)
#include <cuda_runtime.h>
#include <math.h>

#define D 128
#define GMAX 512
#define NMAX 50176

typedef unsigned long long ull;

// ---------------- scratch ----------------
__device__ float g_agg1[NMAX * D];
__device__ float g_agg2[NMAX * D];
__device__ float g_h[NMAX * D];
__device__ float g_h1[NMAX * D];
__device__ float g_sum[2 * D];
__device__ float g_sq[2 * D];
__device__ float g_pa1[GMAX * D];
__device__ float g_pa2[GMAX * D];
__device__ unsigned int g_pm1[GMAX * D];
__device__ unsigned int g_pm2[GMAX * D];

// ---------------- f32x2 helpers ----------------
__device__ __forceinline__ ull ffma2(ull a, ull b, ull c) {
    ull d;
    asm("fma.rn.f32x2 %0, %1, %2, %3;" : "=l"(d) : "l"(a), "l"(b), "l"(c));
    return d;
}
__device__ __forceinline__ ull pack2(float a) {
    ull r; unsigned u = __float_as_uint(a);
    asm("mov.b64 %0, {%1, %1};" : "=l"(r) : "r"(u));
    return r;
}
__device__ __forceinline__ float2 unpack2(ull v) {
    unsigned lo, hi;
    asm("mov.b64 {%0, %1}, %2;" : "=r"(lo), "=r"(hi) : "l"(v));
    return make_float2(__uint_as_float(lo), __uint_as_float(hi));
}
__device__ __forceinline__ void red_add_v4(float* p, float4 v) {
    asm volatile("red.global.add.v4.f32 [%0], {%1,%2,%3,%4};"
                 :: "l"(p), "f"(v.x), "f"(v.y), "f"(v.z), "f"(v.w) : "memory");
}
__device__ __forceinline__ void red_max_u32(unsigned* p, unsigned v) {
    asm volatile("red.global.max.u32 [%0], %1;" :: "l"(p), "r"(v) : "memory");
}

// ---------------- init: zero both agg buffers, pools, stats ----------------
__global__ void init_kernel(float* __restrict__ a1, float* __restrict__ a2,
                            float* __restrict__ pa1, float* __restrict__ pa2,
                            unsigned* __restrict__ pm1, unsigned* __restrict__ pm2,
                            int nd4) {
    int i = blockIdx.x * blockDim.x + threadIdx.x;
    int stride = gridDim.x * blockDim.x;
    float4 z = make_float4(0.f, 0.f, 0.f, 0.f);
    uint4 zu = make_uint4(0u, 0u, 0u, 0u);
    for (int k = i; k < nd4; k += stride) {
        ((float4*)a1)[k] = z;
        ((float4*)a2)[k] = z;
    }
    for (int k = i; k < GMAX * D / 4; k += stride) {
        ((float4*)pa1)[k] = z;
        ((float4*)pa2)[k] = z;
        ((uint4*)pm1)[k] = zu;
        ((uint4*)pm2)[k] = zu;
    }
    if (i < 2 * D) { g_sum[i] = 0.0f; g_sq[i] = 0.0f; }
}

// ---------------- edge scatter: agg[dst] += x[src] (one warp per edge) -----
__global__ void scatter_kernel(const float* __restrict__ x,
                               const int* __restrict__ ei,
                               float* __restrict__ agg, int n_edges, int n) {
    int t = blockIdx.x * blockDim.x + threadIdx.x;
    int e = t >> 5;
    if (e >= n_edges) return;
    int c = t & 31;
    int src = ei[e];
    int dst = ei[n_edges + e];
    if ((unsigned)src >= (unsigned)n || (unsigned)dst >= (unsigned)n) return;
    float4 v = ((const float4*)x)[(size_t)src * 32 + c];
    red_add_v4(agg + (size_t)dst * D + c * 4, v);
}

// =================== GEMM stage 1: h = (agg + x) @ W + b, + BN stats =======
// 128x128 tile, 256 threads, 8x8 per thread via f32x2.
__global__ __launch_bounds__(256) void gemm_stats(
    const float* __restrict__ A, const float* __restrict__ X,
    const float* __restrict__ W, const float* __restrict__ b,
    float* __restrict__ out, float* __restrict__ sumv, float* __restrict__ sqv,
    int n) {
    __shared__ float As[128][36];
    __shared__ float Ws[32][136];
    int t = threadIdx.x;
    int tx = t & 15, ty = t >> 4;
    int r0 = blockIdx.x * 128;

    ull acc[8][4];
#pragma unroll
    for (int i = 0; i < 8; i++)
#pragma unroll
        for (int j = 0; j < 4; j++) acc[i][j] = 0ull;

    for (int kc = 0; kc < 4; kc++) {
#pragma unroll
        for (int i = 0; i < 4; i++) {
            int f = t + i * 256;
            int kk = f >> 5, c4 = (f & 31) * 4;
            *(float4*)&Ws[kk][c4] = *(const float4*)&W[kc * 4096 + kk * 128 + c4];
        }
#pragma unroll
        for (int i = 0; i < 4; i++) {
            int f = t + i * 256;
            int row = f >> 3, c4 = (f & 7) * 4;
            float4 v = make_float4(0.f, 0.f, 0.f, 0.f);
            int r = r0 + row;
            if (r < n) {
                size_t off = (size_t)r * 128 + kc * 32 + c4;
                float4 a = *(const float4*)&A[off];
                float4 x = *(const float4*)&X[off];
                v.x = a.x + x.x; v.y = a.y + x.y;
                v.z = a.z + x.z; v.w = a.w + x.w;
            }
            *(float4*)&As[row][c4] = v;
        }
        __syncthreads();
#pragma unroll 8
        for (int kk = 0; kk < 32; kk++) {
            ull w[4];
#pragma unroll
            for (int j = 0; j < 4; j++) w[j] = *(const ull*)&Ws[kk][tx * 8 + 2 * j];
#pragma unroll
            for (int i = 0; i < 8; i++) {
                ull a2 = pack2(As[ty * 8 + i][kk]);
#pragma unroll
                for (int j = 0; j < 4; j++) acc[i][j] = ffma2(a2, w[j], acc[i][j]);
            }
        }
        __syncthreads();
    }

    // epilogue: bias, store, column stats
    float4 b0 = *(const float4*)&b[tx * 8];
    float4 b1 = *(const float4*)&b[tx * 8 + 4];
    float bias[8] = {b0.x, b0.y, b0.z, b0.w, b1.x, b1.y, b1.z, b1.w};
    float s[8], q[8];
#pragma unroll
    for (int j = 0; j < 8; j++) { s[j] = 0.f; q[j] = 0.f; }

#pragma unroll
    for (int i = 0; i < 8; i++) {
        float o[8];
#pragma unroll
        for (int j = 0; j < 4; j++) {
            float2 p = unpack2(acc[i][j]);
            o[2 * j] = p.x + bias[2 * j];
            o[2 * j + 1] = p.y + bias[2 * j + 1];
        }
        int r = r0 + ty * 8 + i;
        if (r < n) {
            *(float4*)&out[(size_t)r * 128 + tx * 8]     = make_float4(o[0], o[1], o[2], o[3]);
            *(float4*)&out[(size_t)r * 128 + tx * 8 + 4] = make_float4(o[4], o[5], o[6], o[7]);
#pragma unroll
            for (int j = 0; j < 8; j++) { s[j] += o[j]; q[j] += o[j] * o[j]; }
        }
    }

    // cross-thread column reduction in smem (reuse As storage)
    float* redS = &As[0][0];
    float* redQ = &As[0][0] + 2048;
#pragma unroll
    for (int j = 0; j < 8; j++) {
        redS[ty * 128 + tx * 8 + j] = s[j];
        redQ[ty * 128 + tx * 8 + j] = q[j];
    }
    __syncthreads();
    if (t < 128) {
        float ss = 0.f, qq = 0.f;
#pragma unroll
        for (int g = 0; g < 16; g++) {
            ss += redS[g * 128 + t];
            qq += redQ[g * 128 + t];
        }
        atomicAdd(&sumv[t], ss);
        atomicAdd(&sqv[t], qq);
    }
}

// == GEMM stage 2: h1 = relu( relu(scale*h+shift) @ W + b ), fused pooling ==
__global__ __launch_bounds__(256) void gemm_bnrelu(
    const float* __restrict__ A, const float* __restrict__ W,
    const float* __restrict__ b, float* __restrict__ out,
    const int* __restrict__ batch,
    float* __restrict__ psum, unsigned* __restrict__ pmax,
    const float* __restrict__ sumv, const float* __restrict__ sqv,
    const float* __restrict__ gamma, const float* __restrict__ beta,
    int n, int writeH) {
    __shared__ float As[128][36];
    __shared__ float Ws[32][136];
    __shared__ float sc[128];
    __shared__ float sh[128];
    int t = threadIdx.x;
    int tx = t & 15, ty = t >> 4;
    int r0 = blockIdx.x * 128;

    // per-block BN scale/shift from global stats
    if (t < 128) {
        float inv_n = 1.0f / (float)n;
        float mu = sumv[t] * inv_n;
        float var = sqv[t] * inv_n - mu * mu;
        float s = gamma[t] * rsqrtf(var + 1e-5f);
        sc[t] = s;
        sh[t] = beta[t] - mu * s;
    }
    __syncthreads();

    ull acc[8][4];
#pragma unroll
    for (int i = 0; i < 8; i++)
#pragma unroll
        for (int j = 0; j < 4; j++) acc[i][j] = 0ull;

    for (int kc = 0; kc < 4; kc++) {
#pragma unroll
        for (int i = 0; i < 4; i++) {
            int f = t + i * 256;
            int kk = f >> 5, c4 = (f & 31) * 4;
            *(float4*)&Ws[kk][c4] = *(const float4*)&W[kc * 4096 + kk * 128 + c4];
        }
#pragma unroll
        for (int i = 0; i < 4; i++) {
            int f = t + i * 256;
            int row = f >> 3, c4 = (f & 7) * 4;
            float4 v = make_float4(0.f, 0.f, 0.f, 0.f);
            int r = r0 + row;
            int k = kc * 32 + c4;
            if (r < n) {
                float4 h = *(const float4*)&A[(size_t)r * 128 + k];
                v.x = fmaxf(sc[k + 0] * h.x + sh[k + 0], 0.f);
                v.y = fmaxf(sc[k + 1] * h.y + sh[k + 1], 0.f);
                v.z = fmaxf(sc[k + 2] * h.z + sh[k + 2], 0.f);
                v.w = fmaxf(sc[k + 3] * h.w + sh[k + 3], 0.f);
            }
            *(float4*)&As[row][c4] = v;
        }
        __syncthreads();
#pragma unroll 8
        for (int kk = 0; kk < 32; kk++) {
            ull w[4];
#pragma unroll
            for (int j = 0; j < 4; j++) w[j] = *(const ull*)&Ws[kk][tx * 8 + 2 * j];
#pragma unroll
            for (int i = 0; i < 8; i++) {
                ull a2 = pack2(As[ty * 8 + i][kk]);
#pragma unroll
                for (int j = 0; j < 4; j++) acc[i][j] = ffma2(a2, w[j], acc[i][j]);
            }
        }
        __syncthreads();
    }

    float4 b0 = *(const float4*)&b[tx * 8];
    float4 b1 = *(const float4*)&b[tx * 8 + 4];
    float bias[8] = {b0.x, b0.y, b0.z, b0.w, b1.x, b1.y, b1.z, b1.w};

#pragma unroll
    for (int i = 0; i < 8; i++) {
        int r = r0 + ty * 8 + i;
        if (r < n) {
            float o[8];
#pragma unroll
            for (int j = 0; j < 4; j++) {
                float2 p = unpack2(acc[i][j]);
                o[2 * j] = fmaxf(p.x + bias[2 * j], 0.f);
                o[2 * j + 1] = fmaxf(p.y + bias[2 * j + 1], 0.f);
            }
            float4 lo = make_float4(o[0], o[1], o[2], o[3]);
            float4 hi = make_float4(o[4], o[5], o[6], o[7]);
            if (writeH) {
                *(float4*)&out[(size_t)r * 128 + tx * 8]     = lo;
                *(float4*)&out[(size_t)r * 128 + tx * 8 + 4] = hi;
            }
            // fused pooling
            int g = batch[r];
            if ((unsigned)g < GMAX) {
                float* sp = psum + g * D + tx * 8;
                red_add_v4(sp, lo);
                red_add_v4(sp + 4, hi);
                unsigned* mp = pmax + g * D + tx * 8;
                red_max_u32(mp + 0, __float_as_uint(o[0]));
                red_max_u32(mp + 1, __float_as_uint(o[1]));
                red_max_u32(mp + 2, __float_as_uint(o[2]));
                red_max_u32(mp + 3, __float_as_uint(o[3]));
                red_max_u32(mp + 4, __float_as_uint(o[4]));
                red_max_u32(mp + 5, __float_as_uint(o[5]));
                red_max_u32(mp + 6, __float_as_uint(o[6]));
                red_max_u32(mp + 7, __float_as_uint(o[7]));
            }
        }
    }
}

// ---------------- readout ----------------
__global__ __launch_bounds__(512) void readout_kernel(
    const float* __restrict__ W1, const float* __restrict__ b1,
    const float* __restrict__ W2, const float* __restrict__ b2,
    float* __restrict__ out, int Gn, int write_logits) {
    __shared__ float feats[8][512];
    __shared__ float red[512];
    int c = threadIdx.x;
    int g0 = blockIdx.x * 8;

#pragma unroll
    for (int i = 0; i < 8; i++) {
        int g = g0 + i;
        float v = 0.0f;
        if (g < Gn) {
            if (c < 128)      v = g_pa1[g * D + c];
            else if (c < 256) v = g_pa2[g * D + (c - 128)];
            else if (c < 384) v = __uint_as_float(g_pm1[g * D + (c - 256)]);
            else              v = __uint_as_float(g_pm2[g * D + (c - 384)]);
        }
        feats[i][c] = v;
    }
    __syncthreads();

    float acc[8];
#pragma unroll
    for (int i = 0; i < 8; i++) acc[i] = b1[c];

    for (int k = 0; k < 512; k++) {
        float w = W1[k * 512 + c];
#pragma unroll
        for (int i = 0; i < 8; i++) acc[i] += feats[i][k] * w;
    }

    float l2w = W2[c];
    for (int i = 0; i < 8; i++) {
        red[c] = fmaxf(acc[i], 0.0f) * l2w;
        __syncthreads();
        for (int s = 256; s > 0; s >>= 1) {
            if (c < s) red[c] += red[c + s];
            __syncthreads();
        }
        if (c == 0) {
            int g = g0 + i;
            if (g < Gn) {
                float logit = red[0] + b2[0];
                out[g] = 1.0f / (1.0f + expf(-logit));
                if (write_logits) out[Gn + g] = logit;
            }
        }
        __syncthreads();
    }
}

// ---------------- host ----------------
extern "C" void kernel_launch(void* const* d_in, const int* in_sizes, int n_in,
                              void* d_out, int out_size) {
    const float* x     = (const float*)d_in[0];
    const int*   ei    = (const int*)d_in[1];
    const int*   batch = (const int*)d_in[2];
    const float* c1_W1 = (const float*)d_in[3];
    const float* c1_b1 = (const float*)d_in[4];
    const float* c1_g  = (const float*)d_in[5];
    const float* c1_be = (const float*)d_in[6];
    const float* c1_W2 = (const float*)d_in[7];
    const float* c1_b2 = (const float*)d_in[8];
    const float* c2_W1 = (const float*)d_in[9];
    const float* c2_b1 = (const float*)d_in[10];
    const float* c2_g  = (const float*)d_in[11];
    const float* c2_be = (const float*)d_in[12];
    const float* c2_W2 = (const float*)d_in[13];
    const float* c2_b2 = (const float*)d_in[14];
    const float* lin1_W = (const float*)d_in[15];
    const float* lin1_b = (const float*)d_in[16];
    const float* lin2_W = (const float*)d_in[17];
    const float* lin2_b = (const float*)d_in[18];
    float* out = (float*)d_out;

    int n = in_sizes[0] / D;
    int E = in_sizes[1] / 2;
    int Gn, write_logits;
    if (out_size >= 2 * GMAX) { Gn = out_size / 2; write_logits = 1; }
    else                      { Gn = out_size;     write_logits = 0; }

    float *agg1, *agg2, *h, *h1, *pa1, *pa2, *sum, *sq;
    unsigned int *pm1, *pm2;
    cudaGetSymbolAddress((void**)&agg1, g_agg1);
    cudaGetSymbolAddress((void**)&agg2, g_agg2);
    cudaGetSymbolAddress((void**)&h,    g_h);
    cudaGetSymbolAddress((void**)&h1,   g_h1);
    cudaGetSymbolAddress((void**)&pa1,  g_pa1);
    cudaGetSymbolAddress((void**)&pa2,  g_pa2);
    cudaGetSymbolAddress((void**)&pm1,  g_pm1);
    cudaGetSymbolAddress((void**)&pm2,  g_pm2);
    cudaGetSymbolAddress((void**)&sum,  g_sum);
    cudaGetSymbolAddress((void**)&sq,   g_sq);

    int nd4 = n * D / 4;
    int gemmBlocks = (n + 127) / 128;
    int scatterBlocks = (E * 32 + 255) / 256;

    // 0: init everything
    init_kernel<<<1024, 256>>>(agg1, agg2, pa1, pa2, pm1, pm2, nd4);
    // 1-3: conv1
    scatter_kernel<<<scatterBlocks, 256>>>(x, ei, agg1, E, n);
    gemm_stats<<<gemmBlocks, 256>>>(agg1, x, c1_W1, c1_b1, h, sum, sq, n);
    gemm_bnrelu<<<gemmBlocks, 256>>>(h, c1_W2, c1_b2, h1, batch, pa1, pm1,
                                     sum, sq, c1_g, c1_be, n, 1);
    // 4-6: conv2
    scatter_kernel<<<scatterBlocks, 256>>>(h1, ei, agg2, E, n);
    gemm_stats<<<gemmBlocks, 256>>>(agg2, h1, c2_W1, c2_b1, h, sum + D, sq + D, n);
    gemm_bnrelu<<<gemmBlocks, 256>>>(h, c2_W2, c2_b2, (float*)0, batch, pa2, pm2,
                                     sum + D, sq + D, c2_g, c2_be, n, 0);
    // 7: readout
    readout_kernel<<<(Gn + 7) / 8, 512>>>(lin1_W, lin1_b, lin2_W, lin2_b,
                                          out, Gn, write_logits);
}

// round 7
// speedup vs baseline: 1.4430x; 1.4430x over previous
#include <cuda_runtime.h>
#include <cuda_bf16.h>
#include <math.h>
#include <stdint.h>

#define D 128
#define GMAX 512
#define NMAX 50176

typedef unsigned long long ull;

// ---------------- scratch ----------------
__device__ float g_agg1[NMAX * D];
__device__ float g_agg2[NMAX * D];
__device__ float g_h[NMAX * D];
__device__ float g_h1[NMAX * D];
__device__ float g_sum[2 * D];
__device__ float g_sq[2 * D];
__device__ float g_pa1[GMAX * D];
__device__ float g_pa2[GMAX * D];
__device__ unsigned int g_pm1[GMAX * D];
__device__ unsigned int g_pm2[GMAX * D];

// ---------------- helpers ----------------
__device__ __forceinline__ void red_add_v4(float* p, float4 v) {
    asm volatile("red.global.add.v4.f32 [%0], {%1,%2,%3,%4};"
                 :: "l"(p), "f"(v.x), "f"(v.y), "f"(v.z), "f"(v.w) : "memory");
}
__device__ __forceinline__ void red_add_f(float* p, float v) {
    asm volatile("red.global.add.f32 [%0], %1;" :: "l"(p), "f"(v) : "memory");
}
__device__ __forceinline__ void red_max_u32(unsigned* p, unsigned v) {
    asm volatile("red.global.max.u32 [%0], %1;" :: "l"(p), "r"(v) : "memory");
}
__device__ __forceinline__ uint32_t smem_u32(const void* p) {
    uint32_t a;
    asm("{ .reg .u64 t; cvta.to.shared.u64 t, %1; cvt.u32.u64 %0, t; }" : "=r"(a) : "l"(p));
    return a;
}
// split fp32 -> bf16 hi/lo bit patterns
__device__ __forceinline__ void bsplit(float v, unsigned short& hb, unsigned short& lb) {
    __nv_bfloat16 h = __float2bfloat16(v);
    float r = v - __bfloat162float(h);
    __nv_bfloat16 l = __float2bfloat16(r);
    hb = *(unsigned short*)&h;
    lb = *(unsigned short*)&l;
}
__device__ __forceinline__ unsigned pk(unsigned short a, unsigned short b) {
    return (unsigned)a | ((unsigned)b << 16);
}

#define LDSM_X4(r, a)                                                          \
    asm volatile("ldmatrix.sync.aligned.m8n8.x4.shared.b16 {%0,%1,%2,%3}, [%4];" \
                 : "=r"(r[0]), "=r"(r[1]), "=r"(r[2]), "=r"(r[3]) : "r"(a))

#define MMA16816(c, a, b0, b1)                                                 \
    asm volatile("mma.sync.aligned.m16n8k16.row.col.f32.bf16.bf16.f32 "        \
                 "{%0,%1,%2,%3}, {%4,%5,%6,%7}, {%8,%9}, {%0,%1,%2,%3};"       \
                 : "+f"(c[0]), "+f"(c[1]), "+f"(c[2]), "+f"(c[3])              \
                 : "r"(a[0]), "r"(a[1]), "r"(a[2]), "r"(a[3]), "r"(b0), "r"(b1))

// smem byte offsets (dynamic smem)
#define SM_BIAS 0
#define SM_SC   512
#define SM_SH   1024
#define SM_G    1536
#define SM_AHI  2048
#define SM_ALO  36864
#define SM_WHI  71680
#define SM_WLO  106496
#define SM_TOTAL 141312
#define SM_BUF  SM_AHI          // epilogue buffer [128][132] floats (67584 B)

// ---------------- init ----------------
__global__ void init_kernel(float* __restrict__ a1, float* __restrict__ a2,
                            float* __restrict__ pa1, float* __restrict__ pa2,
                            unsigned* __restrict__ pm1, unsigned* __restrict__ pm2,
                            int nd4) {
    int i = blockIdx.x * blockDim.x + threadIdx.x;
    int stride = gridDim.x * blockDim.x;
    float4 z = make_float4(0.f, 0.f, 0.f, 0.f);
    uint4 zu = make_uint4(0u, 0u, 0u, 0u);
    for (int k = i; k < nd4; k += stride) {
        ((float4*)a1)[k] = z;
        ((float4*)a2)[k] = z;
    }
    for (int k = i; k < GMAX * D / 4; k += stride) {
        ((float4*)pa1)[k] = z;
        ((float4*)pa2)[k] = z;
        ((uint4*)pm1)[k] = zu;
        ((uint4*)pm2)[k] = zu;
    }
    if (i < 2 * D) { g_sum[i] = 0.0f; g_sq[i] = 0.0f; }
}

// ---------------- edge scatter ----------------
__global__ void scatter_kernel(const float* __restrict__ x,
                               const int* __restrict__ ei,
                               float* __restrict__ agg, int n_edges, int n) {
    int t = blockIdx.x * blockDim.x + threadIdx.x;
    int e = t >> 5;
    if (e >= n_edges) return;
    int c = t & 31;
    int src = ei[e];
    int dst = ei[n_edges + e];
    if ((unsigned)src >= (unsigned)n || (unsigned)dst >= (unsigned)n) return;
    float4 v = ((const float4*)x)[(size_t)src * 32 + c];
    red_add_v4(agg + (size_t)dst * D + c * 4, v);
}

// ---- shared device routines -------------------------------------------------
// Load W [K=128][N=128] fp32 row-major -> smem Wt hi/lo [n][k] pitch-136 bf16.
__device__ __forceinline__ void load_w(char* smem, const float* __restrict__ W, int tid) {
    for (int i = 0; i < 32; i++) {
        int idx = tid + i * 256;       // 0..8191
        int nn = idx & 127;
        int k2 = (idx >> 7) * 2;
        float v0 = W[k2 * 128 + nn];
        float v1 = W[(k2 + 1) * 128 + nn];
        unsigned short h0, l0, h1, l1;
        bsplit(v0, h0, l0);
        bsplit(v1, h1, l1);
        unsigned boff = (unsigned)(nn * 136 + k2) * 2;
        *(unsigned*)(smem + SM_WHI + boff) = pk(h0, h1);
        *(unsigned*)(smem + SM_WLO + boff) = pk(l0, l1);
    }
}

// mainloop: 8 warps compute C[128][128] += (Ahi+Alo) @ (Whi+Wlo)^T (3-term)
__device__ __forceinline__ void mma_mainloop(uint32_t sbase, int warp, int lane,
                                             float c[16][4]) {
    int wrow = warp * 16;
    uint32_t a_row_off = (uint32_t)((wrow + (lane & 15)) * 136 + ((lane >> 4) << 3)) * 2;
    uint32_t b_row_base = (uint32_t)(((lane & 7) + ((lane >> 4) << 3)) * 136 +
                                     (((lane >> 3) & 1) << 3)) * 2;
    for (int ks = 0; ks < 8; ks++) {
        uint32_t akoff = a_row_off + ks * 32;   // +16 halves
        uint32_t ahi[4], alo[4];
        LDSM_X4(ahi, sbase + SM_AHI + akoff);
        LDSM_X4(alo, sbase + SM_ALO + akoff);
#pragma unroll
        for (int np = 0; np < 8; np++) {
            uint32_t boff = b_row_base + (uint32_t)(np * 16 * 136) * 2 + ks * 32;
            uint32_t bh[4], bl[4];
            LDSM_X4(bh, sbase + SM_WHI + boff);
            LDSM_X4(bl, sbase + SM_WLO + boff);
            MMA16816(c[2 * np],     ahi, bh[0], bh[1]);
            MMA16816(c[2 * np + 1], ahi, bh[2], bh[3]);
            MMA16816(c[2 * np],     ahi, bl[0], bl[1]);
            MMA16816(c[2 * np + 1], ahi, bl[2], bl[3]);
            MMA16816(c[2 * np],     alo, bh[0], bh[1]);
            MMA16816(c[2 * np + 1], alo, bh[2], bh[3]);
        }
    }
}

// write C fragments to smem buffer [128][132] floats
__device__ __forceinline__ void frag_to_buf(float* buf, int warp, int lane,
                                            float c[16][4]) {
    int wrow = warp * 16;
#pragma unroll
    for (int nt = 0; nt < 16; nt++) {
        int col = nt * 8 + (lane & 3) * 2;
        int row = wrow + (lane >> 2);
        *(float2*)&buf[row * 132 + col]       = make_float2(c[nt][0], c[nt][1]);
        *(float2*)&buf[(row + 8) * 132 + col] = make_float2(c[nt][2], c[nt][3]);
    }
}

// =================== GEMM stage 1: h = (agg + x) @ W + b, + BN stats =======
__global__ __launch_bounds__(256) void gemm_stats(
    const float* __restrict__ A, const float* __restrict__ X,
    const float* __restrict__ W, const float* __restrict__ b,
    float* __restrict__ out, float* __restrict__ sumv, float* __restrict__ sqv,
    int n) {
    extern __shared__ __align__(1024) char smem[];
    uint32_t sbase = smem_u32(smem);
    int tid = threadIdx.x;
    int warp = tid >> 5, lane = tid & 31;
    int r0 = blockIdx.x * 128;

    if (tid < 128) ((float*)(smem + SM_BIAS))[tid] = b[tid];

    load_w(smem, W, tid);

    // A rows: (agg + x) -> bf16 hi/lo pitch-136
    for (int i = 0; i < 32; i++) {
        int idx = tid + i * 256;      // 0..8191
        int row = idx >> 6;
        int q = idx & 63;             // float2 index within row
        int r = r0 + row;
        float2 v = make_float2(0.f, 0.f);
        if (r < n) {
            float2 a = ((const float2*)A)[(size_t)r * 64 + q];
            float2 x = ((const float2*)X)[(size_t)r * 64 + q];
            v.x = a.x + x.x;
            v.y = a.y + x.y;
        }
        unsigned short h0, l0, h1, l1;
        bsplit(v.x, h0, l0);
        bsplit(v.y, h1, l1);
        unsigned boff = (unsigned)(row * 136 + q * 2) * 2;
        *(unsigned*)(smem + SM_AHI + boff) = pk(h0, h1);
        *(unsigned*)(smem + SM_ALO + boff) = pk(l0, l1);
    }
    __syncthreads();

    float c[16][4];
#pragma unroll
    for (int i = 0; i < 16; i++)
#pragma unroll
        for (int j = 0; j < 4; j++) c[i][j] = 0.f;

    mma_mainloop(sbase, warp, lane, c);
    __syncthreads();   // done reading A/W smem

    float* buf = (float*)(smem + SM_BUF);
    frag_to_buf(buf, warp, lane, c);
    __syncthreads();

    if (tid < 128) {
        int t = tid;
        float bias_t = ((const float*)(smem + SM_BIAS))[t];
        float s = 0.f, q = 0.f;
        int rmax = n - r0;
        if (rmax > 128) rmax = 128;
        for (int row = 0; row < rmax; row++) {
            float o = buf[row * 132 + t] + bias_t;
            out[(size_t)(r0 + row) * 128 + t] = o;
            s += o;
            q += o * o;
        }
        atomicAdd(&sumv[t], s);
        atomicAdd(&sqv[t], q);
    }
}

// ====== GEMM stage 2: out = relu( relu(bn(h)) @ W + b ), fused pooling =====
__global__ __launch_bounds__(256) void gemm_bnrelu(
    const float* __restrict__ H, const float* __restrict__ W,
    const float* __restrict__ b, float* __restrict__ out,
    const int* __restrict__ batch,
    float* __restrict__ psum, unsigned* __restrict__ pmax,
    const float* __restrict__ sumv, const float* __restrict__ sqv,
    const float* __restrict__ gamma, const float* __restrict__ beta,
    int n, int writeH) {
    extern __shared__ __align__(1024) char smem[];
    uint32_t sbase = smem_u32(smem);
    int tid = threadIdx.x;
    int warp = tid >> 5, lane = tid & 31;
    int r0 = blockIdx.x * 128;

    if (tid < 128) {
        ((float*)(smem + SM_BIAS))[tid] = b[tid];
        float inv_n = 1.0f / (float)n;
        float mu = sumv[tid] * inv_n;
        float var = sqv[tid] * inv_n - mu * mu;
        float s = gamma[tid] * rsqrtf(var + 1e-5f);
        ((float*)(smem + SM_SC))[tid] = s;
        ((float*)(smem + SM_SH))[tid] = beta[tid] - mu * s;
        ((int*)(smem + SM_G))[tid] = (r0 + tid < n) ? batch[r0 + tid] : -1;
    }
    load_w(smem, W, tid);
    __syncthreads();   // sc/sh ready before A conversion

    const float* sc = (const float*)(smem + SM_SC);
    const float* sh = (const float*)(smem + SM_SH);

    for (int i = 0; i < 32; i++) {
        int idx = tid + i * 256;
        int row = idx >> 6;
        int q = idx & 63;
        int r = r0 + row;
        int k = q * 2;
        float2 v = make_float2(0.f, 0.f);
        if (r < n) {
            float2 h = ((const float2*)H)[(size_t)r * 64 + q];
            v.x = fmaxf(sc[k] * h.x + sh[k], 0.f);
            v.y = fmaxf(sc[k + 1] * h.y + sh[k + 1], 0.f);
        }
        unsigned short h0, l0, h1, l1;
        bsplit(v.x, h0, l0);
        bsplit(v.y, h1, l1);
        unsigned boff = (unsigned)(row * 136 + k) * 2;
        *(unsigned*)(smem + SM_AHI + boff) = pk(h0, h1);
        *(unsigned*)(smem + SM_ALO + boff) = pk(l0, l1);
    }
    __syncthreads();

    float c[16][4];
#pragma unroll
    for (int i = 0; i < 16; i++)
#pragma unroll
        for (int j = 0; j < 4; j++) c[i][j] = 0.f;

    mma_mainloop(sbase, warp, lane, c);
    __syncthreads();

    float* buf = (float*)(smem + SM_BUF);
    frag_to_buf(buf, warp, lane, c);
    __syncthreads();

    if (tid < 128) {
        int t = tid;
        float bias_t = ((const float*)(smem + SM_BIAS))[t];
        const int* gsm = (const int*)(smem + SM_G);
        int rmax = n - r0;
        if (rmax > 128) rmax = 128;
        int cur = -1;
        float rs = 0.f, rm = 0.f;
        for (int row = 0; row < rmax; row++) {
            float o = fmaxf(buf[row * 132 + t] + bias_t, 0.f);
            if (writeH) out[(size_t)(r0 + row) * 128 + t] = o;
            int g = gsm[row];
            if (g != cur) {
                if (cur >= 0 && cur < GMAX) {
                    red_add_f(&psum[(size_t)cur * 128 + t], rs);
                    red_max_u32(&pmax[(size_t)cur * 128 + t], __float_as_uint(rm));
                }
                cur = g;
                rs = 0.f;
                rm = 0.f;
            }
            rs += o;
            rm = fmaxf(rm, o);
        }
        if (cur >= 0 && cur < GMAX) {
            red_add_f(&psum[(size_t)cur * 128 + t], rs);
            red_max_u32(&pmax[(size_t)cur * 128 + t], __float_as_uint(rm));
        }
    }
}

// ---------------- readout ----------------
__global__ __launch_bounds__(512) void readout_kernel(
    const float* __restrict__ W1, const float* __restrict__ b1,
    const float* __restrict__ W2, const float* __restrict__ b2,
    float* __restrict__ out, int Gn, int write_logits) {
    __shared__ float feats[8][512];
    __shared__ float red[512];
    int c = threadIdx.x;
    int g0 = blockIdx.x * 8;

#pragma unroll
    for (int i = 0; i < 8; i++) {
        int g = g0 + i;
        float v = 0.0f;
        if (g < Gn) {
            if (c < 128)      v = g_pa1[g * D + c];
            else if (c < 256) v = g_pa2[g * D + (c - 128)];
            else if (c < 384) v = __uint_as_float(g_pm1[g * D + (c - 256)]);
            else              v = __uint_as_float(g_pm2[g * D + (c - 384)]);
        }
        feats[i][c] = v;
    }
    __syncthreads();

    float acc[8];
#pragma unroll
    for (int i = 0; i < 8; i++) acc[i] = b1[c];

    for (int k = 0; k < 512; k++) {
        float w = W1[k * 512 + c];
#pragma unroll
        for (int i = 0; i < 8; i++) acc[i] += feats[i][k] * w;
    }

    float l2w = W2[c];
    for (int i = 0; i < 8; i++) {
        red[c] = fmaxf(acc[i], 0.0f) * l2w;
        __syncthreads();
        for (int s = 256; s > 0; s >>= 1) {
            if (c < s) red[c] += red[c + s];
            __syncthreads();
        }
        if (c == 0) {
            int g = g0 + i;
            if (g < Gn) {
                float logit = red[0] + b2[0];
                out[g] = 1.0f / (1.0f + expf(-logit));
                if (write_logits) out[Gn + g] = logit;
            }
        }
        __syncthreads();
    }
}

// ---------------- host ----------------
extern "C" void kernel_launch(void* const* d_in, const int* in_sizes, int n_in,
                              void* d_out, int out_size) {
    const float* x     = (const float*)d_in[0];
    const int*   ei    = (const int*)d_in[1];
    const int*   batch = (const int*)d_in[2];
    const float* c1_W1 = (const float*)d_in[3];
    const float* c1_b1 = (const float*)d_in[4];
    const float* c1_g  = (const float*)d_in[5];
    const float* c1_be = (const float*)d_in[6];
    const float* c1_W2 = (const float*)d_in[7];
    const float* c1_b2 = (const float*)d_in[8];
    const float* c2_W1 = (const float*)d_in[9];
    const float* c2_b1 = (const float*)d_in[10];
    const float* c2_g  = (const float*)d_in[11];
    const float* c2_be = (const float*)d_in[12];
    const float* c2_W2 = (const float*)d_in[13];
    const float* c2_b2 = (const float*)d_in[14];
    const float* lin1_W = (const float*)d_in[15];
    const float* lin1_b = (const float*)d_in[16];
    const float* lin2_W = (const float*)d_in[17];
    const float* lin2_b = (const float*)d_in[18];
    float* out = (float*)d_out;

    int n = in_sizes[0] / D;
    int E = in_sizes[1] / 2;
    int Gn, write_logits;
    if (out_size >= 2 * GMAX) { Gn = out_size / 2; write_logits = 1; }
    else                      { Gn = out_size;     write_logits = 0; }

    float *agg1, *agg2, *h, *h1, *pa1, *pa2, *sum, *sq;
    unsigned int *pm1, *pm2;
    cudaGetSymbolAddress((void**)&agg1, g_agg1);
    cudaGetSymbolAddress((void**)&agg2, g_agg2);
    cudaGetSymbolAddress((void**)&h,    g_h);
    cudaGetSymbolAddress((void**)&h1,   g_h1);
    cudaGetSymbolAddress((void**)&pa1,  g_pa1);
    cudaGetSymbolAddress((void**)&pa2,  g_pa2);
    cudaGetSymbolAddress((void**)&pm1,  g_pm1);
    cudaGetSymbolAddress((void**)&pm2,  g_pm2);
    cudaGetSymbolAddress((void**)&sum,  g_sum);
    cudaGetSymbolAddress((void**)&sq,   g_sq);

    cudaFuncSetAttribute(gemm_stats, cudaFuncAttributeMaxDynamicSharedMemorySize, SM_TOTAL);
    cudaFuncSetAttribute(gemm_bnrelu, cudaFuncAttributeMaxDynamicSharedMemorySize, SM_TOTAL);

    int nd4 = n * D / 4;
    int gemmBlocks = (n + 127) / 128;
    int scatterBlocks = (E * 32 + 255) / 256;

    // 0: init
    init_kernel<<<1024, 256>>>(agg1, agg2, pa1, pa2, pm1, pm2, nd4);
    // 1-3: conv1
    scatter_kernel<<<scatterBlocks, 256>>>(x, ei, agg1, E, n);
    gemm_stats<<<gemmBlocks, 256, SM_TOTAL>>>(agg1, x, c1_W1, c1_b1, h, sum, sq, n);
    gemm_bnrelu<<<gemmBlocks, 256, SM_TOTAL>>>(h, c1_W2, c1_b2, h1, batch, pa1, pm1,
                                               sum, sq, c1_g, c1_be, n, 1);
    // 4-6: conv2
    scatter_kernel<<<scatterBlocks, 256>>>(h1, ei, agg2, E, n);
    gemm_stats<<<gemmBlocks, 256, SM_TOTAL>>>(agg2, h1, c2_W1, c2_b1, h, sum + D, sq + D, n);
    gemm_bnrelu<<<gemmBlocks, 256, SM_TOTAL>>>(h, c2_W2, c2_b2, (float*)0, batch, pa2, pm2,
                                               sum + D, sq + D, c2_g, c2_be, n, 0);
    // 7: readout
    readout_kernel<<<(Gn + 7) / 8, 512>>>(lin1_W, lin1_b, lin2_W, lin2_b,
                                          out, Gn, write_logits);
}

// round 8
// speedup vs baseline: 1.6552x; 1.1470x over previous
#include <cuda_runtime.h>
#include <cuda_bf16.h>
#include <math.h>
#include <stdint.h>

#define D 128
#define GMAX 512
#define NMAX 50176

typedef unsigned long long ull;

// ---------------- scratch ----------------
__device__ float g_agg1[NMAX * D];
__device__ float g_agg2[NMAX * D];
__device__ float g_h[NMAX * D];
__device__ float g_h1[NMAX * D];
__device__ float g_sum[2 * D];
__device__ float g_sq[2 * D];
__device__ float g_pa1[GMAX * D];
__device__ float g_pa2[GMAX * D];
__device__ unsigned int g_pm1[GMAX * D];
__device__ unsigned int g_pm2[GMAX * D];
// pre-split, pre-laid-out W images: [weight][hi/lo][128 n-rows * 136 pitch halves]
__device__ unsigned short g_wimg[4][2][17408];

// ---------------- helpers ----------------
__device__ __forceinline__ void red_add_v4(float* p, float4 v) {
    asm volatile("red.global.add.v4.f32 [%0], {%1,%2,%3,%4};"
                 :: "l"(p), "f"(v.x), "f"(v.y), "f"(v.z), "f"(v.w) : "memory");
}
__device__ __forceinline__ void red_add_f(float* p, float v) {
    asm volatile("red.global.add.f32 [%0], %1;" :: "l"(p), "f"(v) : "memory");
}
__device__ __forceinline__ void red_max_u32(unsigned* p, unsigned v) {
    asm volatile("red.global.max.u32 [%0], %1;" :: "l"(p), "r"(v) : "memory");
}
__device__ __forceinline__ uint32_t smem_u32(const void* p) {
    uint32_t a;
    asm("{ .reg .u64 t; cvta.to.shared.u64 t, %1; cvt.u32.u64 %0, t; }" : "=r"(a) : "l"(p));
    return a;
}
__device__ __forceinline__ void bsplit(float v, unsigned short& hb, unsigned short& lb) {
    __nv_bfloat16 h = __float2bfloat16(v);
    float r = v - __bfloat162float(h);
    __nv_bfloat16 l = __float2bfloat16(r);
    hb = *(unsigned short*)&h;
    lb = *(unsigned short*)&l;
}
__device__ __forceinline__ unsigned pk(unsigned short a, unsigned short b) {
    return (unsigned)a | ((unsigned)b << 16);
}

#define LDSM_X4(r, a)                                                          \
    asm volatile("ldmatrix.sync.aligned.m8n8.x4.shared.b16 {%0,%1,%2,%3}, [%4];" \
                 : "=r"(r[0]), "=r"(r[1]), "=r"(r[2]), "=r"(r[3]) : "r"(a))

#define MMA16816(c, a, b0, b1)                                                 \
    asm volatile("mma.sync.aligned.m16n8k16.row.col.f32.bf16.bf16.f32 "        \
                 "{%0,%1,%2,%3}, {%4,%5,%6,%7}, {%8,%9}, {%0,%1,%2,%3};"       \
                 : "+f"(c[0]), "+f"(c[1]), "+f"(c[2]), "+f"(c[3])              \
                 : "r"(a[0]), "r"(a[1]), "r"(a[2]), "r"(a[3]), "r"(b0), "r"(b1))

#define CP_ASYNC16(sa, gp) \
    asm volatile("cp.async.cg.shared.global [%0], [%1], 16;" :: "r"(sa), "l"(gp))
#define CP_COMMIT() asm volatile("cp.async.commit_group;")
#define CP_WAIT0()  asm volatile("cp.async.wait_group 0;" ::: "memory")

// smem byte offsets
#define SM_BIAS 0
#define SM_SC   512
#define SM_SH   1024
#define SM_G    1536
#define SM_AHI  2048            // 128 rows * 72 halves * 2B = 18432
#define SM_ALO  20480           // 18432
#define SM_WHI  38912           // 128 * 136 * 2 = 34816
#define SM_WLO  73728           // 34816
#define SM_TOTAL 108544
#define SM_BUF  SM_AHI          // epilogue buffer [128][132] floats (67584 B, aliases A+WHI)

// ---------------- init ----------------
__global__ void init_kernel(float* __restrict__ a1, float* __restrict__ a2,
                            float* __restrict__ pa1, float* __restrict__ pa2,
                            unsigned* __restrict__ pm1, unsigned* __restrict__ pm2,
                            int nd4) {
    int i = blockIdx.x * blockDim.x + threadIdx.x;
    int stride = gridDim.x * blockDim.x;
    float4 z = make_float4(0.f, 0.f, 0.f, 0.f);
    uint4 zu = make_uint4(0u, 0u, 0u, 0u);
    for (int k = i; k < nd4; k += stride) {
        ((float4*)a1)[k] = z;
        ((float4*)a2)[k] = z;
    }
    for (int k = i; k < GMAX * D / 4; k += stride) {
        ((float4*)pa1)[k] = z;
        ((float4*)pa2)[k] = z;
        ((uint4*)pm1)[k] = zu;
        ((uint4*)pm2)[k] = zu;
    }
    if (i < 2 * D) { g_sum[i] = 0.0f; g_sq[i] = 0.0f; }
}

// ---------------- weight prep: W [K][N] fp32 -> Wt [n][k] bf16 hi/lo pitch-136
__global__ void prep_w(const float* __restrict__ W0, const float* __restrict__ W1,
                       const float* __restrict__ W2, const float* __restrict__ W3) {
    const float* Ws[4] = {W0, W1, W2, W3};
    const float* W = Ws[blockIdx.x];
    unsigned short* hi = g_wimg[blockIdx.x][0];
    unsigned short* lo = g_wimg[blockIdx.x][1];
    for (int idx = threadIdx.x; idx < 16384; idx += blockDim.x) {
        int nr = idx >> 7, k = idx & 127;
        unsigned short hb, lb;
        bsplit(W[k * 128 + nr], hb, lb);
        hi[nr * 136 + k] = hb;
        lo[nr * 136 + k] = lb;
    }
}

// ---------------- edge scatter ----------------
__global__ void scatter_kernel(const float* __restrict__ x,
                               const int* __restrict__ ei,
                               float* __restrict__ agg, int n_edges, int n) {
    int t = blockIdx.x * blockDim.x + threadIdx.x;
    int e = t >> 5;
    if (e >= n_edges) return;
    int c = t & 31;
    int src = ei[e];
    int dst = ei[n_edges + e];
    if ((unsigned)src >= (unsigned)n || (unsigned)dst >= (unsigned)n) return;
    float4 v = ((const float4*)x)[(size_t)src * 32 + c];
    red_add_v4(agg + (size_t)dst * D + c * 4, v);
}

// ---- shared device routines -----------------------------------------------
// start async copy of both W images (69632 B total, contiguous hi then lo)
__device__ __forceinline__ void w_copy_async(uint32_t sbase, const unsigned short* wimg, int tid) {
    const char* src = (const char*)wimg;
#pragma unroll
    for (int i = 0; i < 17; i++) {
        int c16 = tid + i * 256;
        if (c16 < 4352) CP_ASYNC16(sbase + SM_WHI + c16 * 16, src + c16 * 16);
    }
    CP_COMMIT();
}

// mainloop over one K-half (4 ksteps of 16)
__device__ __forceinline__ void mma_half(uint32_t sbase, int warp, int lane, int half,
                                         float c[16][4]) {
    int wrow = warp * 16;
    uint32_t a_row_off = (uint32_t)((wrow + (lane & 15)) * 72 + ((lane >> 4) << 3)) * 2;
    uint32_t b_row_base = (uint32_t)(((lane & 7) + ((lane >> 4) << 3)) * 136 +
                                     (((lane >> 3) & 1) << 3)) * 2;
    for (int ks = 0; ks < 4; ks++) {
        uint32_t akoff = a_row_off + ks * 32;
        uint32_t ahi[4], alo[4];
        LDSM_X4(ahi, sbase + SM_AHI + akoff);
        LDSM_X4(alo, sbase + SM_ALO + akoff);
        uint32_t wkoff = (uint32_t)(half * 128 + ks * 32);
#pragma unroll
        for (int np = 0; np < 8; np++) {
            uint32_t boff = b_row_base + (uint32_t)(np * 16 * 136) * 2 + wkoff;
            uint32_t bh[4], bl[4];
            LDSM_X4(bh, sbase + SM_WHI + boff);
            LDSM_X4(bl, sbase + SM_WLO + boff);
            MMA16816(c[2 * np],     ahi, bh[0], bh[1]);
            MMA16816(c[2 * np + 1], ahi, bh[2], bh[3]);
            MMA16816(c[2 * np],     ahi, bl[0], bl[1]);
            MMA16816(c[2 * np + 1], ahi, bl[2], bl[3]);
            MMA16816(c[2 * np],     alo, bh[0], bh[1]);
            MMA16816(c[2 * np + 1], alo, bh[2], bh[3]);
        }
    }
}

__device__ __forceinline__ void frag_to_buf(float* buf, int warp, int lane,
                                            float c[16][4]) {
    int wrow = warp * 16;
#pragma unroll
    for (int nt = 0; nt < 16; nt++) {
        int col = nt * 8 + (lane & 3) * 2;
        int row = wrow + (lane >> 2);
        *(float2*)&buf[row * 132 + col]       = make_float2(c[nt][0], c[nt][1]);
        *(float2*)&buf[(row + 8) * 132 + col] = make_float2(c[nt][2], c[nt][3]);
    }
}

// =================== GEMM stage 1: h = (agg + x) @ W + b, + BN stats =======
__global__ __launch_bounds__(256, 2) void gemm_stats(
    const float* __restrict__ A, const float* __restrict__ X,
    const unsigned short* __restrict__ wimg, const float* __restrict__ b,
    float* __restrict__ out, float* __restrict__ sumv, float* __restrict__ sqv,
    int n) {
    extern __shared__ __align__(1024) char smem[];
    uint32_t sbase = smem_u32(smem);
    int tid = threadIdx.x;
    int warp = tid >> 5, lane = tid & 31;
    int r0 = blockIdx.x * 128;

    if (tid < 128) ((float*)(smem + SM_BIAS))[tid] = b[tid];
    w_copy_async(sbase, wimg, tid);

    float c[16][4];
#pragma unroll
    for (int i = 0; i < 16; i++)
#pragma unroll
        for (int j = 0; j < 4; j++) c[i][j] = 0.f;

    for (int half = 0; half < 2; half++) {
        // convert A K-half -> bf16 hi/lo pitch-72
#pragma unroll
        for (int i = 0; i < 16; i++) {
            int idx = tid + i * 256;       // 0..4095
            int row = idx >> 5;
            int q = idx & 31;              // float2 idx within half-row
            int r = r0 + row;
            float2 v = make_float2(0.f, 0.f);
            if (r < n) {
                float2 a = ((const float2*)A)[(size_t)r * 64 + half * 32 + q];
                float2 x = ((const float2*)X)[(size_t)r * 64 + half * 32 + q];
                v.x = a.x + x.x;
                v.y = a.y + x.y;
            }
            unsigned short h0, l0, h1, l1;
            bsplit(v.x, h0, l0);
            bsplit(v.y, h1, l1);
            unsigned boff = (unsigned)(row * 72 + q * 2) * 2;
            *(unsigned*)(smem + SM_AHI + boff) = pk(h0, h1);
            *(unsigned*)(smem + SM_ALO + boff) = pk(l0, l1);
        }
        if (half == 0) CP_WAIT0();
        __syncthreads();
        mma_half(sbase, warp, lane, half, c);
        __syncthreads();
    }

    float* buf = (float*)(smem + SM_BUF);
    frag_to_buf(buf, warp, lane, c);
    __syncthreads();

    if (tid < 128) {
        int t = tid;
        float bias_t = ((const float*)(smem + SM_BIAS))[t];
        float s = 0.f, q = 0.f;
        int rmax = n - r0;
        if (rmax > 128) rmax = 128;
        for (int row = 0; row < rmax; row++) {
            float o = buf[row * 132 + t] + bias_t;
            out[(size_t)(r0 + row) * 128 + t] = o;
            s += o;
            q += o * o;
        }
        atomicAdd(&sumv[t], s);
        atomicAdd(&sqv[t], q);
    }
}

// ====== GEMM stage 2: out = relu( relu(bn(h)) @ W + b ), fused pooling =====
__global__ __launch_bounds__(256, 2) void gemm_bnrelu(
    const float* __restrict__ H,
    const unsigned short* __restrict__ wimg, const float* __restrict__ b,
    float* __restrict__ out, const int* __restrict__ batch,
    float* __restrict__ psum, unsigned* __restrict__ pmax,
    const float* __restrict__ sumv, const float* __restrict__ sqv,
    const float* __restrict__ gamma, const float* __restrict__ beta,
    int n, int writeH) {
    extern __shared__ __align__(1024) char smem[];
    uint32_t sbase = smem_u32(smem);
    int tid = threadIdx.x;
    int warp = tid >> 5, lane = tid & 31;
    int r0 = blockIdx.x * 128;

    if (tid < 128) {
        ((float*)(smem + SM_BIAS))[tid] = b[tid];
        float inv_n = 1.0f / (float)n;
        float mu = sumv[tid] * inv_n;
        float var = sqv[tid] * inv_n - mu * mu;
        float s = gamma[tid] * rsqrtf(var + 1e-5f);
        ((float*)(smem + SM_SC))[tid] = s;
        ((float*)(smem + SM_SH))[tid] = beta[tid] - mu * s;
        ((int*)(smem + SM_G))[tid] = (r0 + tid < n) ? batch[r0 + tid] : -1;
    }
    w_copy_async(sbase, wimg, tid);
    __syncthreads();   // sc/sh visible before A conversion

    const float* sc = (const float*)(smem + SM_SC);
    const float* sh = (const float*)(smem + SM_SH);

    float c[16][4];
#pragma unroll
    for (int i = 0; i < 16; i++)
#pragma unroll
        for (int j = 0; j < 4; j++) c[i][j] = 0.f;

    for (int half = 0; half < 2; half++) {
#pragma unroll
        for (int i = 0; i < 16; i++) {
            int idx = tid + i * 256;
            int row = idx >> 5;
            int q = idx & 31;
            int r = r0 + row;
            int k = half * 64 + q * 2;
            float2 v = make_float2(0.f, 0.f);
            if (r < n) {
                float2 h = ((const float2*)H)[(size_t)r * 64 + half * 32 + q];
                v.x = fmaxf(sc[k] * h.x + sh[k], 0.f);
                v.y = fmaxf(sc[k + 1] * h.y + sh[k + 1], 0.f);
            }
            unsigned short h0, l0, h1, l1;
            bsplit(v.x, h0, l0);
            bsplit(v.y, h1, l1);
            unsigned boff = (unsigned)(row * 72 + q * 2) * 2;
            *(unsigned*)(smem + SM_AHI + boff) = pk(h0, h1);
            *(unsigned*)(smem + SM_ALO + boff) = pk(l0, l1);
        }
        if (half == 0) CP_WAIT0();
        __syncthreads();
        mma_half(sbase, warp, lane, half, c);
        __syncthreads();
    }

    float* buf = (float*)(smem + SM_BUF);
    frag_to_buf(buf, warp, lane, c);
    __syncthreads();

    if (tid < 128) {
        int t = tid;
        float bias_t = ((const float*)(smem + SM_BIAS))[t];
        const int* gsm = (const int*)(smem + SM_G);
        int rmax = n - r0;
        if (rmax > 128) rmax = 128;
        int cur = -1;
        float rs = 0.f, rm = 0.f;
        for (int row = 0; row < rmax; row++) {
            float o = fmaxf(buf[row * 132 + t] + bias_t, 0.f);
            if (writeH) out[(size_t)(r0 + row) * 128 + t] = o;
            int g = gsm[row];
            if (g != cur) {
                if (cur >= 0 && cur < GMAX) {
                    red_add_f(&psum[(size_t)cur * 128 + t], rs);
                    red_max_u32(&pmax[(size_t)cur * 128 + t], __float_as_uint(rm));
                }
                cur = g;
                rs = 0.f;
                rm = 0.f;
            }
            rs += o;
            rm = fmaxf(rm, o);
        }
        if (cur >= 0 && cur < GMAX) {
            red_add_f(&psum[(size_t)cur * 128 + t], rs);
            red_max_u32(&pmax[(size_t)cur * 128 + t], __float_as_uint(rm));
        }
    }
}

// ---------------- readout ----------------
__global__ __launch_bounds__(512) void readout_kernel(
    const float* __restrict__ W1, const float* __restrict__ b1,
    const float* __restrict__ W2, const float* __restrict__ b2,
    float* __restrict__ out, int Gn, int write_logits) {
    __shared__ float feats[8][512];
    __shared__ float red[512];
    int c = threadIdx.x;
    int g0 = blockIdx.x * 8;

#pragma unroll
    for (int i = 0; i < 8; i++) {
        int g = g0 + i;
        float v = 0.0f;
        if (g < Gn) {
            if (c < 128)      v = g_pa1[g * D + c];
            else if (c < 256) v = g_pa2[g * D + (c - 128)];
            else if (c < 384) v = __uint_as_float(g_pm1[g * D + (c - 256)]);
            else              v = __uint_as_float(g_pm2[g * D + (c - 384)]);
        }
        feats[i][c] = v;
    }
    __syncthreads();

    float acc[8];
#pragma unroll
    for (int i = 0; i < 8; i++) acc[i] = b1[c];

    for (int k = 0; k < 512; k++) {
        float w = W1[k * 512 + c];
#pragma unroll
        for (int i = 0; i < 8; i++) acc[i] += feats[i][k] * w;
    }

    float l2w = W2[c];
    for (int i = 0; i < 8; i++) {
        red[c] = fmaxf(acc[i], 0.0f) * l2w;
        __syncthreads();
        for (int s = 256; s > 0; s >>= 1) {
            if (c < s) red[c] += red[c + s];
            __syncthreads();
        }
        if (c == 0) {
            int g = g0 + i;
            if (g < Gn) {
                float logit = red[0] + b2[0];
                out[g] = 1.0f / (1.0f + expf(-logit));
                if (write_logits) out[Gn + g] = logit;
            }
        }
        __syncthreads();
    }
}

// ---------------- host ----------------
extern "C" void kernel_launch(void* const* d_in, const int* in_sizes, int n_in,
                              void* d_out, int out_size) {
    const float* x     = (const float*)d_in[0];
    const int*   ei    = (const int*)d_in[1];
    const int*   batch = (const int*)d_in[2];
    const float* c1_W1 = (const float*)d_in[3];
    const float* c1_b1 = (const float*)d_in[4];
    const float* c1_g  = (const float*)d_in[5];
    const float* c1_be = (const float*)d_in[6];
    const float* c1_W2 = (const float*)d_in[7];
    const float* c1_b2 = (const float*)d_in[8];
    const float* c2_W1 = (const float*)d_in[9];
    const float* c2_b1 = (const float*)d_in[10];
    const float* c2_g  = (const float*)d_in[11];
    const float* c2_be = (const float*)d_in[12];
    const float* c2_W2 = (const float*)d_in[13];
    const float* c2_b2 = (const float*)d_in[14];
    const float* lin1_W = (const float*)d_in[15];
    const float* lin1_b = (const float*)d_in[16];
    const float* lin2_W = (const float*)d_in[17];
    const float* lin2_b = (const float*)d_in[18];
    float* out = (float*)d_out;

    int n = in_sizes[0] / D;
    int E = in_sizes[1] / 2;
    int Gn, write_logits;
    if (out_size >= 2 * GMAX) { Gn = out_size / 2; write_logits = 1; }
    else                      { Gn = out_size;     write_logits = 0; }

    float *agg1, *agg2, *h, *h1, *pa1, *pa2, *sum, *sq;
    unsigned int *pm1, *pm2;
    unsigned short* wimg;
    cudaGetSymbolAddress((void**)&agg1, g_agg1);
    cudaGetSymbolAddress((void**)&agg2, g_agg2);
    cudaGetSymbolAddress((void**)&h,    g_h);
    cudaGetSymbolAddress((void**)&h1,   g_h1);
    cudaGetSymbolAddress((void**)&pa1,  g_pa1);
    cudaGetSymbolAddress((void**)&pa2,  g_pa2);
    cudaGetSymbolAddress((void**)&pm1,  g_pm1);
    cudaGetSymbolAddress((void**)&pm2,  g_pm2);
    cudaGetSymbolAddress((void**)&sum,  g_sum);
    cudaGetSymbolAddress((void**)&sq,   g_sq);
    cudaGetSymbolAddress((void**)&wimg, g_wimg);

    cudaFuncSetAttribute(gemm_stats, cudaFuncAttributeMaxDynamicSharedMemorySize, SM_TOTAL);
    cudaFuncSetAttribute(gemm_bnrelu, cudaFuncAttributeMaxDynamicSharedMemorySize, SM_TOTAL);

    int nd4 = n * D / 4;
    int gemmBlocks = (n + 127) / 128;
    int scatterBlocks = (E * 32 + 255) / 256;

    const unsigned short* w0 = wimg + 0 * 2 * 17408;
    const unsigned short* w1 = wimg + 1 * 2 * 17408;
    const unsigned short* w2 = wimg + 2 * 2 * 17408;
    const unsigned short* w3 = wimg + 3 * 2 * 17408;

    // 0-1: init + weight prep
    init_kernel<<<1024, 256>>>(agg1, agg2, pa1, pa2, pm1, pm2, nd4);
    prep_w<<<4, 256>>>(c1_W1, c1_W2, c2_W1, c2_W2);
    // 2-4: conv1
    scatter_kernel<<<scatterBlocks, 256>>>(x, ei, agg1, E, n);
    gemm_stats<<<gemmBlocks, 256, SM_TOTAL>>>(agg1, x, w0, c1_b1, h, sum, sq, n);
    gemm_bnrelu<<<gemmBlocks, 256, SM_TOTAL>>>(h, w1, c1_b2, h1, batch, pa1, pm1,
                                               sum, sq, c1_g, c1_be, n, 1);
    // 5-7: conv2
    scatter_kernel<<<scatterBlocks, 256>>>(h1, ei, agg2, E, n);
    gemm_stats<<<gemmBlocks, 256, SM_TOTAL>>>(agg2, h1, w2, c2_b1, h, sum + D, sq + D, n);
    gemm_bnrelu<<<gemmBlocks, 256, SM_TOTAL>>>(h, w3, c2_b2, (float*)0, batch, pa2, pm2,
                                               sum + D, sq + D, c2_g, c2_be, n, 0);
    // 8: readout
    readout_kernel<<<(Gn + 7) / 8, 512>>>(lin1_W, lin1_b, lin2_W, lin2_b,
                                          out, Gn, write_logits);
}

// round 9
// speedup vs baseline: 2.0598x; 1.2445x over previous
#include <cuda_runtime.h>
#include <cuda_bf16.h>
#include <math.h>
#include <stdint.h>

#define D 128
#define GMAX 512
#define NMAX 50176
#define EMAX 655360

typedef unsigned long long ull;

// ---------------- scratch ----------------
__device__ float g_agg1[NMAX * D];
__device__ float g_agg2[NMAX * D];
__device__ float g_h[NMAX * D];
__device__ float g_h1[NMAX * D];
__device__ float g_sum[2 * D];
__device__ float g_sq[2 * D];
__device__ float g_pa1[GMAX * D];
__device__ float g_pa2[GMAX * D];
__device__ unsigned int g_pm1[GMAX * D];
__device__ unsigned int g_pm2[GMAX * D];
__device__ int g_head[NMAX];
__device__ int g_nxt[EMAX];
// pre-split W images: [weight][hi/lo][128 n-rows * 136 pitch halves]
__device__ unsigned short g_wimg[4][2][17408];

// ---------------- helpers ----------------
__device__ __forceinline__ void red_add_f(float* p, float v) {
    asm volatile("red.global.add.f32 [%0], %1;" :: "l"(p), "f"(v) : "memory");
}
__device__ __forceinline__ void red_max_u32(unsigned* p, unsigned v) {
    asm volatile("red.global.max.u32 [%0], %1;" :: "l"(p), "r"(v) : "memory");
}
__device__ __forceinline__ uint32_t smem_u32(const void* p) {
    uint32_t a;
    asm("{ .reg .u64 t; cvta.to.shared.u64 t, %1; cvt.u32.u64 %0, t; }" : "=r"(a) : "l"(p));
    return a;
}
__device__ __forceinline__ void bsplit(float v, unsigned short& hb, unsigned short& lb) {
    __nv_bfloat16 h = __float2bfloat16(v);
    float r = v - __bfloat162float(h);
    __nv_bfloat16 l = __float2bfloat16(r);
    hb = *(unsigned short*)&h;
    lb = *(unsigned short*)&l;
}
__device__ __forceinline__ unsigned pk(unsigned short a, unsigned short b) {
    return (unsigned)a | ((unsigned)b << 16);
}

#define LDSM_X4(r, a)                                                          \
    asm volatile("ldmatrix.sync.aligned.m8n8.x4.shared.b16 {%0,%1,%2,%3}, [%4];" \
                 : "=r"(r[0]), "=r"(r[1]), "=r"(r[2]), "=r"(r[3]) : "r"(a))

#define MMA16816(c, a, b0, b1)                                                 \
    asm volatile("mma.sync.aligned.m16n8k16.row.col.f32.bf16.bf16.f32 "        \
                 "{%0,%1,%2,%3}, {%4,%5,%6,%7}, {%8,%9}, {%0,%1,%2,%3};"       \
                 : "+f"(c[0]), "+f"(c[1]), "+f"(c[2]), "+f"(c[3])              \
                 : "r"(a[0]), "r"(a[1]), "r"(a[2]), "r"(a[3]), "r"(b0), "r"(b1))

#define CP_ASYNC16(sa, gp) \
    asm volatile("cp.async.cg.shared.global [%0], [%1], 16;" :: "r"(sa), "l"(gp))
#define CP_COMMIT() asm volatile("cp.async.commit_group;")
#define CP_WAIT0()  asm volatile("cp.async.wait_group 0;" ::: "memory")

// smem byte offsets
#define SM_BIAS 0
#define SM_SC   512
#define SM_SH   1024
#define SM_G    1536
#define SM_AHI  2048            // 128 rows * 72 halves * 2B = 18432
#define SM_ALO  20480           // 18432
#define SM_WHI  38912           // 128 * 136 * 2 = 34816
#define SM_WLO  73728           // 34816
#define SM_TOTAL 108544
#define SM_BUF  SM_AHI          // epilogue buffer [128][132] floats, aliases A+WHI

// ---------------- init: pools, stats, list heads ----------------
__global__ void init_kernel(float* __restrict__ pa1, float* __restrict__ pa2,
                            unsigned* __restrict__ pm1, unsigned* __restrict__ pm2,
                            int* __restrict__ head, int n) {
    int i = blockIdx.x * blockDim.x + threadIdx.x;
    int stride = gridDim.x * blockDim.x;
    float4 z = make_float4(0.f, 0.f, 0.f, 0.f);
    uint4 zu = make_uint4(0u, 0u, 0u, 0u);
    for (int k = i; k < GMAX * D / 4; k += stride) {
        ((float4*)pa1)[k] = z;
        ((float4*)pa2)[k] = z;
        ((uint4*)pm1)[k] = zu;
        ((uint4*)pm2)[k] = zu;
    }
    for (int k = i; k < n; k += stride) head[k] = -1;
    if (i < 2 * D) { g_sum[i] = 0.0f; g_sq[i] = 0.0f; }
}

// ---------------- weight prep ----------------
__global__ void prep_w(const float* __restrict__ W0, const float* __restrict__ W1,
                       const float* __restrict__ W2, const float* __restrict__ W3) {
    const float* Ws[4] = {W0, W1, W2, W3};
    const float* W = Ws[blockIdx.x];
    unsigned short* hi = g_wimg[blockIdx.x][0];
    unsigned short* lo = g_wimg[blockIdx.x][1];
    for (int idx = threadIdx.x; idx < 16384; idx += blockDim.x) {
        int nr = idx >> 7, k = idx & 127;
        unsigned short hb, lb;
        bsplit(W[k * 128 + nr], hb, lb);
        hi[nr * 136 + k] = hb;
        lo[nr * 136 + k] = lb;
    }
}

// ---------------- build per-dst incoming edge list (once per launch) -------
__global__ void build_list(const int* __restrict__ ei, int* __restrict__ head,
                           int* __restrict__ nxt, int nE, int n) {
    int e = blockIdx.x * blockDim.x + threadIdx.x;
    if (e >= nE) return;
    int src = ei[e];
    int dst = ei[nE + e];
    if ((unsigned)src >= (unsigned)n || (unsigned)dst >= (unsigned)n) return;
    nxt[e] = atomicExch(&head[dst], e);
}

// ---------------- gather: agg[v] = x[v] + sum_{e: dst==v} x[src[e]] -------
__global__ void gather_kernel(const float* __restrict__ x,
                              const int* __restrict__ ei,
                              const int* __restrict__ head,
                              const int* __restrict__ nxt,
                              float* __restrict__ agg, int n) {
    int t = blockIdx.x * blockDim.x + threadIdx.x;
    int v = t >> 5;
    if (v >= n) return;
    int c = t & 31;
    float4 acc = ((const float4*)x)[(size_t)v * 32 + c];
    int e = head[v];
    while (e >= 0) {
        int src = __ldg(&ei[e]);
        float4 xv = ((const float4*)x)[(size_t)src * 32 + c];
        acc.x += xv.x; acc.y += xv.y; acc.z += xv.z; acc.w += xv.w;
        e = __ldg(&nxt[e]);
    }
    ((float4*)agg)[(size_t)v * 32 + c] = acc;
}

// ---- GEMM shared routines --------------------------------------------------
__device__ __forceinline__ void w_copy_async(uint32_t sbase, const unsigned short* wimg, int tid) {
    const char* src = (const char*)wimg;
#pragma unroll
    for (int i = 0; i < 17; i++) {
        int c16 = tid + i * 256;
        if (c16 < 4352) CP_ASYNC16(sbase + SM_WHI + c16 * 16, src + c16 * 16);
    }
    CP_COMMIT();
}

__device__ __forceinline__ void mma_half(uint32_t sbase, int warp, int lane, int half,
                                         float c[16][4]) {
    int wrow = warp * 16;
    uint32_t a_row_off = (uint32_t)((wrow + (lane & 15)) * 72 + ((lane >> 4) << 3)) * 2;
    uint32_t b_row_base = (uint32_t)(((lane & 7) + ((lane >> 4) << 3)) * 136 +
                                     (((lane >> 3) & 1) << 3)) * 2;
    for (int ks = 0; ks < 4; ks++) {
        uint32_t akoff = a_row_off + ks * 32;
        uint32_t ahi[4], alo[4];
        LDSM_X4(ahi, sbase + SM_AHI + akoff);
        LDSM_X4(alo, sbase + SM_ALO + akoff);
        uint32_t wkoff = (uint32_t)(half * 128 + ks * 32);
#pragma unroll
        for (int np = 0; np < 8; np++) {
            uint32_t boff = b_row_base + (uint32_t)(np * 16 * 136) * 2 + wkoff;
            uint32_t bh[4], bl[4];
            LDSM_X4(bh, sbase + SM_WHI + boff);
            LDSM_X4(bl, sbase + SM_WLO + boff);
            MMA16816(c[2 * np],     ahi, bh[0], bh[1]);
            MMA16816(c[2 * np + 1], ahi, bh[2], bh[3]);
            MMA16816(c[2 * np],     ahi, bl[0], bl[1]);
            MMA16816(c[2 * np + 1], ahi, bl[2], bl[3]);
            MMA16816(c[2 * np],     alo, bh[0], bh[1]);
            MMA16816(c[2 * np + 1], alo, bh[2], bh[3]);
        }
    }
}

__device__ __forceinline__ void frag_to_buf(float* buf, int warp, int lane,
                                            float c[16][4]) {
    int wrow = warp * 16;
#pragma unroll
    for (int nt = 0; nt < 16; nt++) {
        int col = nt * 8 + (lane & 3) * 2;
        int row = wrow + (lane >> 2);
        *(float2*)&buf[row * 132 + col]       = make_float2(c[nt][0], c[nt][1]);
        *(float2*)&buf[(row + 8) * 132 + col] = make_float2(c[nt][2], c[nt][3]);
    }
}

// =================== GEMM stage 1: h = A @ W + b, + BN stats ===============
__global__ __launch_bounds__(256, 2) void gemm_stats(
    const float* __restrict__ A,
    const unsigned short* __restrict__ wimg, const float* __restrict__ b,
    float* __restrict__ out, float* __restrict__ sumv, float* __restrict__ sqv,
    int n) {
    extern __shared__ __align__(1024) char smem[];
    uint32_t sbase = smem_u32(smem);
    int tid = threadIdx.x;
    int warp = tid >> 5, lane = tid & 31;
    int r0 = blockIdx.x * 128;

    if (tid < 128) ((float*)(smem + SM_BIAS))[tid] = b[tid];
    w_copy_async(sbase, wimg, tid);

    float c[16][4];
#pragma unroll
    for (int i = 0; i < 16; i++)
#pragma unroll
        for (int j = 0; j < 4; j++) c[i][j] = 0.f;

    for (int half = 0; half < 2; half++) {
#pragma unroll
        for (int i = 0; i < 16; i++) {
            int idx = tid + i * 256;
            int row = idx >> 5;
            int q = idx & 31;
            int r = r0 + row;
            float2 v = make_float2(0.f, 0.f);
            if (r < n) v = ((const float2*)A)[(size_t)r * 64 + half * 32 + q];
            unsigned short h0, l0, h1, l1;
            bsplit(v.x, h0, l0);
            bsplit(v.y, h1, l1);
            unsigned boff = (unsigned)(row * 72 + q * 2) * 2;
            *(unsigned*)(smem + SM_AHI + boff) = pk(h0, h1);
            *(unsigned*)(smem + SM_ALO + boff) = pk(l0, l1);
        }
        if (half == 0) CP_WAIT0();
        __syncthreads();
        mma_half(sbase, warp, lane, half, c);
        __syncthreads();
    }

    float* buf = (float*)(smem + SM_BUF);
    frag_to_buf(buf, warp, lane, c);
    __syncthreads();

    if (tid < 128) {
        int t = tid;
        float bias_t = ((const float*)(smem + SM_BIAS))[t];
        float s = 0.f, q = 0.f;
        int rmax = n - r0;
        if (rmax > 128) rmax = 128;
        for (int row = 0; row < rmax; row++) {
            float o = buf[row * 132 + t] + bias_t;
            out[(size_t)(r0 + row) * 128 + t] = o;
            s += o;
            q += o * o;
        }
        atomicAdd(&sumv[t], s);
        atomicAdd(&sqv[t], q);
    }
}

// ====== GEMM stage 2: out = relu( relu(bn(h)) @ W + b ), fused pooling =====
__global__ __launch_bounds__(256, 2) void gemm_bnrelu(
    const float* __restrict__ H,
    const unsigned short* __restrict__ wimg, const float* __restrict__ b,
    float* __restrict__ out, const int* __restrict__ batch,
    float* __restrict__ psum, unsigned* __restrict__ pmax,
    const float* __restrict__ sumv, const float* __restrict__ sqv,
    const float* __restrict__ gamma, const float* __restrict__ beta,
    int n, int writeH) {
    extern __shared__ __align__(1024) char smem[];
    uint32_t sbase = smem_u32(smem);
    int tid = threadIdx.x;
    int warp = tid >> 5, lane = tid & 31;
    int r0 = blockIdx.x * 128;

    if (tid < 128) {
        ((float*)(smem + SM_BIAS))[tid] = b[tid];
        float inv_n = 1.0f / (float)n;
        float mu = sumv[tid] * inv_n;
        float var = sqv[tid] * inv_n - mu * mu;
        float s = gamma[tid] * rsqrtf(var + 1e-5f);
        ((float*)(smem + SM_SC))[tid] = s;
        ((float*)(smem + SM_SH))[tid] = beta[tid] - mu * s;
        ((int*)(smem + SM_G))[tid] = (r0 + tid < n) ? batch[r0 + tid] : -1;
    }
    w_copy_async(sbase, wimg, tid);
    __syncthreads();

    const float* sc = (const float*)(smem + SM_SC);
    const float* sh = (const float*)(smem + SM_SH);

    float c[16][4];
#pragma unroll
    for (int i = 0; i < 16; i++)
#pragma unroll
        for (int j = 0; j < 4; j++) c[i][j] = 0.f;

    for (int half = 0; half < 2; half++) {
#pragma unroll
        for (int i = 0; i < 16; i++) {
            int idx = tid + i * 256;
            int row = idx >> 5;
            int q = idx & 31;
            int r = r0 + row;
            int k = half * 64 + q * 2;
            float2 v = make_float2(0.f, 0.f);
            if (r < n) {
                float2 h = ((const float2*)H)[(size_t)r * 64 + half * 32 + q];
                v.x = fmaxf(sc[k] * h.x + sh[k], 0.f);
                v.y = fmaxf(sc[k + 1] * h.y + sh[k + 1], 0.f);
            }
            unsigned short h0, l0, h1, l1;
            bsplit(v.x, h0, l0);
            bsplit(v.y, h1, l1);
            unsigned boff = (unsigned)(row * 72 + q * 2) * 2;
            *(unsigned*)(smem + SM_AHI + boff) = pk(h0, h1);
            *(unsigned*)(smem + SM_ALO + boff) = pk(l0, l1);
        }
        if (half == 0) CP_WAIT0();
        __syncthreads();
        mma_half(sbase, warp, lane, half, c);
        __syncthreads();
    }

    float* buf = (float*)(smem + SM_BUF);
    frag_to_buf(buf, warp, lane, c);
    __syncthreads();

    if (tid < 128) {
        int t = tid;
        float bias_t = ((const float*)(smem + SM_BIAS))[t];
        const int* gsm = (const int*)(smem + SM_G);
        int rmax = n - r0;
        if (rmax > 128) rmax = 128;
        int cur = -1;
        float rs = 0.f, rm = 0.f;
        for (int row = 0; row < rmax; row++) {
            float o = fmaxf(buf[row * 132 + t] + bias_t, 0.f);
            if (writeH) out[(size_t)(r0 + row) * 128 + t] = o;
            int g = gsm[row];
            if (g != cur) {
                if (cur >= 0 && cur < GMAX) {
                    red_add_f(&psum[(size_t)cur * 128 + t], rs);
                    red_max_u32(&pmax[(size_t)cur * 128 + t], __float_as_uint(rm));
                }
                cur = g;
                rs = 0.f;
                rm = 0.f;
            }
            rs += o;
            rm = fmaxf(rm, o);
        }
        if (cur >= 0 && cur < GMAX) {
            red_add_f(&psum[(size_t)cur * 128 + t], rs);
            red_max_u32(&pmax[(size_t)cur * 128 + t], __float_as_uint(rm));
        }
    }
}

// ---------------- readout ----------------
__global__ __launch_bounds__(512) void readout_kernel(
    const float* __restrict__ W1, const float* __restrict__ b1,
    const float* __restrict__ W2, const float* __restrict__ b2,
    float* __restrict__ out, int Gn, int write_logits) {
    __shared__ float feats[8][512];
    __shared__ float red[512];
    int c = threadIdx.x;
    int g0 = blockIdx.x * 8;

#pragma unroll
    for (int i = 0; i < 8; i++) {
        int g = g0 + i;
        float v = 0.0f;
        if (g < Gn) {
            if (c < 128)      v = g_pa1[g * D + c];
            else if (c < 256) v = g_pa2[g * D + (c - 128)];
            else if (c < 384) v = __uint_as_float(g_pm1[g * D + (c - 256)]);
            else              v = __uint_as_float(g_pm2[g * D + (c - 384)]);
        }
        feats[i][c] = v;
    }
    __syncthreads();

    float acc[8];
#pragma unroll
    for (int i = 0; i < 8; i++) acc[i] = b1[c];

    for (int k = 0; k < 512; k++) {
        float w = W1[k * 512 + c];
#pragma unroll
        for (int i = 0; i < 8; i++) acc[i] += feats[i][k] * w;
    }

    float l2w = W2[c];
    for (int i = 0; i < 8; i++) {
        red[c] = fmaxf(acc[i], 0.0f) * l2w;
        __syncthreads();
        for (int s = 256; s > 0; s >>= 1) {
            if (c < s) red[c] += red[c + s];
            __syncthreads();
        }
        if (c == 0) {
            int g = g0 + i;
            if (g < Gn) {
                float logit = red[0] + b2[0];
                out[g] = 1.0f / (1.0f + expf(-logit));
                if (write_logits) out[Gn + g] = logit;
            }
        }
        __syncthreads();
    }
}

// ---------------- host ----------------
extern "C" void kernel_launch(void* const* d_in, const int* in_sizes, int n_in,
                              void* d_out, int out_size) {
    const float* x     = (const float*)d_in[0];
    const int*   ei    = (const int*)d_in[1];
    const int*   batch = (const int*)d_in[2];
    const float* c1_W1 = (const float*)d_in[3];
    const float* c1_b1 = (const float*)d_in[4];
    const float* c1_g  = (const float*)d_in[5];
    const float* c1_be = (const float*)d_in[6];
    const float* c1_W2 = (const float*)d_in[7];
    const float* c1_b2 = (const float*)d_in[8];
    const float* c2_W1 = (const float*)d_in[9];
    const float* c2_b1 = (const float*)d_in[10];
    const float* c2_g  = (const float*)d_in[11];
    const float* c2_be = (const float*)d_in[12];
    const float* c2_W2 = (const float*)d_in[13];
    const float* c2_b2 = (const float*)d_in[14];
    const float* lin1_W = (const float*)d_in[15];
    const float* lin1_b = (const float*)d_in[16];
    const float* lin2_W = (const float*)d_in[17];
    const float* lin2_b = (const float*)d_in[18];
    float* out = (float*)d_out;

    int n = in_sizes[0] / D;
    int E = in_sizes[1] / 2;
    if (E > EMAX) E = EMAX;
    int Gn, write_logits;
    if (out_size >= 2 * GMAX) { Gn = out_size / 2; write_logits = 1; }
    else                      { Gn = out_size;     write_logits = 0; }

    float *agg1, *agg2, *h, *h1, *pa1, *pa2, *sum, *sq;
    unsigned int *pm1, *pm2;
    unsigned short* wimg;
    int *head, *nxt;
    cudaGetSymbolAddress((void**)&agg1, g_agg1);
    cudaGetSymbolAddress((void**)&agg2, g_agg2);
    cudaGetSymbolAddress((void**)&h,    g_h);
    cudaGetSymbolAddress((void**)&h1,   g_h1);
    cudaGetSymbolAddress((void**)&pa1,  g_pa1);
    cudaGetSymbolAddress((void**)&pa2,  g_pa2);
    cudaGetSymbolAddress((void**)&pm1,  g_pm1);
    cudaGetSymbolAddress((void**)&pm2,  g_pm2);
    cudaGetSymbolAddress((void**)&sum,  g_sum);
    cudaGetSymbolAddress((void**)&sq,   g_sq);
    cudaGetSymbolAddress((void**)&wimg, g_wimg);
    cudaGetSymbolAddress((void**)&head, g_head);
    cudaGetSymbolAddress((void**)&nxt,  g_nxt);

    cudaFuncSetAttribute(gemm_stats, cudaFuncAttributeMaxDynamicSharedMemorySize, SM_TOTAL);
    cudaFuncSetAttribute(gemm_bnrelu, cudaFuncAttributeMaxDynamicSharedMemorySize, SM_TOTAL);

    int gemmBlocks = (n + 127) / 128;
    int gatherBlocks = (n * 32 + 255) / 256;
    int edgeBlocks = (E + 255) / 256;

    const unsigned short* w0 = wimg + 0 * 2 * 17408;
    const unsigned short* w1 = wimg + 1 * 2 * 17408;
    const unsigned short* w2 = wimg + 2 * 2 * 17408;
    const unsigned short* w3 = wimg + 3 * 2 * 17408;

    // 0-2: init + weight prep + edge list build
    init_kernel<<<512, 256>>>(pa1, pa2, pm1, pm2, head, n);
    prep_w<<<4, 256>>>(c1_W1, c1_W2, c2_W1, c2_W2);
    build_list<<<edgeBlocks, 256>>>(ei, head, nxt, E, n);
    // 3-5: conv1
    gather_kernel<<<gatherBlocks, 256>>>(x, ei, head, nxt, agg1, n);
    gemm_stats<<<gemmBlocks, 256, SM_TOTAL>>>(agg1, w0, c1_b1, h, sum, sq, n);
    gemm_bnrelu<<<gemmBlocks, 256, SM_TOTAL>>>(h, w1, c1_b2, h1, batch, pa1, pm1,
                                               sum, sq, c1_g, c1_be, n, 1);
    // 6-8: conv2
    gather_kernel<<<gatherBlocks, 256>>>(h1, ei, head, nxt, agg2, n);
    gemm_stats<<<gemmBlocks, 256, SM_TOTAL>>>(agg2, w2, c2_b1, h, sum + D, sq + D, n);
    gemm_bnrelu<<<gemmBlocks, 256, SM_TOTAL>>>(h, w3, c2_b2, (float*)0, batch, pa2, pm2,
                                               sum + D, sq + D, c2_g, c2_be, n, 0);
    // 9: readout
    readout_kernel<<<(Gn + 7) / 8, 512>>>(lin1_W, lin1_b, lin2_W, lin2_b,
                                          out, Gn, write_logits);
}

// round 10
// speedup vs baseline: 2.1662x; 1.0517x over previous
#include <cuda_runtime.h>
#include <cuda_bf16.h>
#include <math.h>
#include <stdint.h>

#define D 128
#define GMAX 512
#define NMAX 50176
#define EMAX 655360

typedef unsigned long long ull;

// ---------------- scratch ----------------
__device__ float g_agg1[NMAX * D];
__device__ float g_agg2[NMAX * D];
__device__ float g_h[NMAX * D];
__device__ float g_h1[NMAX * D];
__device__ float g_sum[2 * D];
__device__ float g_sq[2 * D];
__device__ float g_pa1[GMAX * D];
__device__ float g_pa2[GMAX * D];
__device__ unsigned int g_pm1[GMAX * D];
__device__ unsigned int g_pm2[GMAX * D];
__device__ int g_head[NMAX];
__device__ int g_nxt[EMAX];
// pre-split W images: [weight][hi/lo][128 n-rows * 136 pitch halves]
__device__ unsigned short g_wimg[4][2][17408];

// ---------------- helpers ----------------
__device__ __forceinline__ void red_add_f(float* p, float v) {
    asm volatile("red.global.add.f32 [%0], %1;" :: "l"(p), "f"(v) : "memory");
}
__device__ __forceinline__ void red_max_u32(unsigned* p, unsigned v) {
    asm volatile("red.global.max.u32 [%0], %1;" :: "l"(p), "r"(v) : "memory");
}
__device__ __forceinline__ uint32_t smem_u32(const void* p) {
    uint32_t a;
    asm("{ .reg .u64 t; cvta.to.shared.u64 t, %1; cvt.u32.u64 %0, t; }" : "=r"(a) : "l"(p));
    return a;
}
__device__ __forceinline__ void bsplit(float v, unsigned short& hb, unsigned short& lb) {
    __nv_bfloat16 h = __float2bfloat16(v);
    float r = v - __bfloat162float(h);
    __nv_bfloat16 l = __float2bfloat16(r);
    hb = *(unsigned short*)&h;
    lb = *(unsigned short*)&l;
}
__device__ __forceinline__ unsigned pk(unsigned short a, unsigned short b) {
    return (unsigned)a | ((unsigned)b << 16);
}

#define LDSM_X4(r, a)                                                          \
    asm volatile("ldmatrix.sync.aligned.m8n8.x4.shared.b16 {%0,%1,%2,%3}, [%4];" \
                 : "=r"(r[0]), "=r"(r[1]), "=r"(r[2]), "=r"(r[3]) : "r"(a))

#define MMA16816(c, a, b0, b1)                                                 \
    asm volatile("mma.sync.aligned.m16n8k16.row.col.f32.bf16.bf16.f32 "        \
                 "{%0,%1,%2,%3}, {%4,%5,%6,%7}, {%8,%9}, {%0,%1,%2,%3};"       \
                 : "+f"(c[0]), "+f"(c[1]), "+f"(c[2]), "+f"(c[3])              \
                 : "r"(a[0]), "r"(a[1]), "r"(a[2]), "r"(a[3]), "r"(b0), "r"(b1))

#define CP_ASYNC16(sa, gp) \
    asm volatile("cp.async.cg.shared.global [%0], [%1], 16;" :: "r"(sa), "l"(gp))
#define CP_COMMIT() asm volatile("cp.async.commit_group;")
#define CP_WAIT0()  asm volatile("cp.async.wait_group 0;" ::: "memory")

// smem byte offsets
#define SM_BIAS 0
#define SM_SC   512
#define SM_SH   1024
#define SM_G    1536
#define SM_AHI  2048            // 128 rows * 72 halves * 2B = 18432
#define SM_ALO  20480
#define SM_WHI  38912           // 128 * 136 * 2 = 34816
#define SM_WLO  73728
#define SM_TOTAL 108544
#define SM_BUF  SM_AHI          // epilogue buffer [128][132] floats, aliases A+WHI

// ------- init: pools, stats, list heads; blocks 512..515 do weight prep ----
__global__ void init_kernel(float* __restrict__ pa1, float* __restrict__ pa2,
                            unsigned* __restrict__ pm1, unsigned* __restrict__ pm2,
                            int* __restrict__ head, int n,
                            const float* __restrict__ W0, const float* __restrict__ W1,
                            const float* __restrict__ W2, const float* __restrict__ W3) {
    if (blockIdx.x >= 512) {
        int wi = blockIdx.x - 512;
        const float* Ws[4] = {W0, W1, W2, W3};
        const float* W = Ws[wi];
        unsigned short* hi = g_wimg[wi][0];
        unsigned short* lo = g_wimg[wi][1];
        for (int idx = threadIdx.x; idx < 16384; idx += blockDim.x) {
            int nr = idx >> 7, k = idx & 127;
            unsigned short hb, lb;
            bsplit(W[k * 128 + nr], hb, lb);
            hi[nr * 136 + k] = hb;
            lo[nr * 136 + k] = lb;
        }
        return;
    }
    int i = blockIdx.x * blockDim.x + threadIdx.x;
    int stride = 512 * blockDim.x;
    float4 z = make_float4(0.f, 0.f, 0.f, 0.f);
    uint4 zu = make_uint4(0u, 0u, 0u, 0u);
    for (int k = i; k < GMAX * D / 4; k += stride) {
        ((float4*)pa1)[k] = z;
        ((float4*)pa2)[k] = z;
        ((uint4*)pm1)[k] = zu;
        ((uint4*)pm2)[k] = zu;
    }
    for (int k = i; k < n; k += stride) head[k] = -1;
    if (i < 2 * D) { g_sum[i] = 0.0f; g_sq[i] = 0.0f; }
}

// ---------------- build per-dst incoming edge list (once per launch) -------
__global__ void build_list(const int* __restrict__ ei, int* __restrict__ head,
                           int* __restrict__ nxt, int nE, int n) {
    int e = blockIdx.x * blockDim.x + threadIdx.x;
    if (e >= nE) return;
    int src = ei[e];
    int dst = ei[nE + e];
    if ((unsigned)src >= (unsigned)n || (unsigned)dst >= (unsigned)n) return;
    nxt[e] = atomicExch(&head[dst], e);
}

// --------- gather: agg[v] = x[v] + sum_in x[src]; 2 nodes per warp ---------
__global__ void gather_kernel(const float* __restrict__ x,
                              const int* __restrict__ ei,
                              const int* __restrict__ head,
                              const int* __restrict__ nxt,
                              float* __restrict__ agg, int n) {
    int t = blockIdx.x * blockDim.x + threadIdx.x;
    int v = t >> 4;            // 16 lanes per node
    if (v >= n) return;
    int c = t & 15;            // lane handles float4 pair c*2, c*2+1
    const float4* x4 = (const float4*)x;
    float4 a0 = x4[(size_t)v * 32 + c * 2];
    float4 a1 = x4[(size_t)v * 32 + c * 2 + 1];
    int e = head[v];
    while (e >= 0) {
        int src = __ldg(&ei[e]);
        float4 v0 = x4[(size_t)src * 32 + c * 2];
        float4 v1 = x4[(size_t)src * 32 + c * 2 + 1];
        a0.x += v0.x; a0.y += v0.y; a0.z += v0.z; a0.w += v0.w;
        a1.x += v1.x; a1.y += v1.y; a1.z += v1.z; a1.w += v1.w;
        e = __ldg(&nxt[e]);
    }
    ((float4*)agg)[(size_t)v * 32 + c * 2]     = a0;
    ((float4*)agg)[(size_t)v * 32 + c * 2 + 1] = a1;
}

// ---- GEMM shared routines --------------------------------------------------
__device__ __forceinline__ void w_copy_async(uint32_t sbase, const unsigned short* wimg, int tid) {
    const char* src = (const char*)wimg;
#pragma unroll
    for (int i = 0; i < 17; i++) {
        int c16 = tid + i * 256;
        if (c16 < 4352) CP_ASYNC16(sbase + SM_WHI + c16 * 16, src + c16 * 16);
    }
    CP_COMMIT();
}

__device__ __forceinline__ void mma_half(uint32_t sbase, int warp, int lane, int half,
                                         float c[16][4]) {
    int wrow = warp * 16;
    uint32_t a_row_off = (uint32_t)((wrow + (lane & 15)) * 72 + ((lane >> 4) << 3)) * 2;
    uint32_t b_row_base = (uint32_t)(((lane & 7) + ((lane >> 4) << 3)) * 136 +
                                     (((lane >> 3) & 1) << 3)) * 2;
    for (int ks = 0; ks < 4; ks++) {
        uint32_t akoff = a_row_off + ks * 32;
        uint32_t ahi[4], alo[4];
        LDSM_X4(ahi, sbase + SM_AHI + akoff);
        LDSM_X4(alo, sbase + SM_ALO + akoff);
        uint32_t wkoff = (uint32_t)(half * 128 + ks * 32);
#pragma unroll
        for (int np = 0; np < 8; np++) {
            uint32_t boff = b_row_base + (uint32_t)(np * 16 * 136) * 2 + wkoff;
            uint32_t bh[4], bl[4];
            LDSM_X4(bh, sbase + SM_WHI + boff);
            LDSM_X4(bl, sbase + SM_WLO + boff);
            MMA16816(c[2 * np],     ahi, bh[0], bh[1]);
            MMA16816(c[2 * np + 1], ahi, bh[2], bh[3]);
            MMA16816(c[2 * np],     ahi, bl[0], bl[1]);
            MMA16816(c[2 * np + 1], ahi, bl[2], bl[3]);
            MMA16816(c[2 * np],     alo, bh[0], bh[1]);
            MMA16816(c[2 * np + 1], alo, bh[2], bh[3]);
        }
    }
}

__device__ __forceinline__ void frag_to_buf(float* buf, int warp, int lane,
                                            float c[16][4]) {
    int wrow = warp * 16;
#pragma unroll
    for (int nt = 0; nt < 16; nt++) {
        int col = nt * 8 + (lane & 3) * 2;
        int row = wrow + (lane >> 2);
        *(float2*)&buf[row * 132 + col]       = make_float2(c[nt][0], c[nt][1]);
        *(float2*)&buf[(row + 8) * 132 + col] = make_float2(c[nt][2], c[nt][3]);
    }
}

// =================== GEMM stage 1: h = A @ W + b, + BN stats ===============
__global__ __launch_bounds__(256, 2) void gemm_stats(
    const float* __restrict__ A,
    const unsigned short* __restrict__ wimg, const float* __restrict__ b,
    float* __restrict__ out, float* __restrict__ sumv, float* __restrict__ sqv,
    int n) {
    extern __shared__ __align__(1024) char smem[];
    uint32_t sbase = smem_u32(smem);
    int tid = threadIdx.x;
    int warp = tid >> 5, lane = tid & 31;
    int r0 = blockIdx.x * 128;

    if (tid < 128) ((float*)(smem + SM_BIAS))[tid] = b[tid];
    w_copy_async(sbase, wimg, tid);

    float c[16][4];
#pragma unroll
    for (int i = 0; i < 16; i++)
#pragma unroll
        for (int j = 0; j < 4; j++) c[i][j] = 0.f;

    for (int half = 0; half < 2; half++) {
#pragma unroll
        for (int i = 0; i < 16; i++) {
            int idx = tid + i * 256;
            int row = idx >> 5;
            int q = idx & 31;
            int r = r0 + row;
            float2 v = make_float2(0.f, 0.f);
            if (r < n) v = ((const float2*)A)[(size_t)r * 64 + half * 32 + q];
            unsigned short h0, l0, h1, l1;
            bsplit(v.x, h0, l0);
            bsplit(v.y, h1, l1);
            unsigned boff = (unsigned)(row * 72 + q * 2) * 2;
            *(unsigned*)(smem + SM_AHI + boff) = pk(h0, h1);
            *(unsigned*)(smem + SM_ALO + boff) = pk(l0, l1);
        }
        if (half == 0) CP_WAIT0();
        __syncthreads();
        mma_half(sbase, warp, lane, half, c);
        __syncthreads();
    }

    float* buf = (float*)(smem + SM_BUF);
    frag_to_buf(buf, warp, lane, c);
    __syncthreads();

    {
        int t = tid & 127;
        int rbeg = (tid >> 7) * 64;
        float bias_t = ((const float*)(smem + SM_BIAS))[t];
        float s = 0.f, q = 0.f;
        int rmax = n - r0;
        if (rmax > 128) rmax = 128;
        int rend = rbeg + 64;
        if (rend > rmax) rend = rmax;
        for (int row = rbeg; row < rend; row++) {
            float o = buf[row * 132 + t] + bias_t;
            out[(size_t)(r0 + row) * 128 + t] = o;
            s += o;
            q += o * o;
        }
        if (rbeg < rend) {
            atomicAdd(&sumv[t], s);
            atomicAdd(&sqv[t], q);
        }
    }
}

// ====== GEMM stage 2: out = relu( relu(bn(h)) @ W + b ), fused pooling =====
__global__ __launch_bounds__(256, 2) void gemm_bnrelu(
    const float* __restrict__ H,
    const unsigned short* __restrict__ wimg, const float* __restrict__ b,
    float* __restrict__ out, const int* __restrict__ batch,
    float* __restrict__ psum, unsigned* __restrict__ pmax,
    const float* __restrict__ sumv, const float* __restrict__ sqv,
    const float* __restrict__ gamma, const float* __restrict__ beta,
    int n, int writeH) {
    extern __shared__ __align__(1024) char smem[];
    uint32_t sbase = smem_u32(smem);
    int tid = threadIdx.x;
    int warp = tid >> 5, lane = tid & 31;
    int r0 = blockIdx.x * 128;

    if (tid < 128) {
        ((float*)(smem + SM_BIAS))[tid] = b[tid];
        float inv_n = 1.0f / (float)n;
        float mu = sumv[tid] * inv_n;
        float var = sqv[tid] * inv_n - mu * mu;
        float s = gamma[tid] * rsqrtf(var + 1e-5f);
        ((float*)(smem + SM_SC))[tid] = s;
        ((float*)(smem + SM_SH))[tid] = beta[tid] - mu * s;
        ((int*)(smem + SM_G))[tid] = (r0 + tid < n) ? batch[r0 + tid] : -1;
    }
    w_copy_async(sbase, wimg, tid);
    __syncthreads();

    const float* sc = (const float*)(smem + SM_SC);
    const float* sh = (const float*)(smem + SM_SH);

    float c[16][4];
#pragma unroll
    for (int i = 0; i < 16; i++)
#pragma unroll
        for (int j = 0; j < 4; j++) c[i][j] = 0.f;

    for (int half = 0; half < 2; half++) {
#pragma unroll
        for (int i = 0; i < 16; i++) {
            int idx = tid + i * 256;
            int row = idx >> 5;
            int q = idx & 31;
            int r = r0 + row;
            int k = half * 64 + q * 2;
            float2 v = make_float2(0.f, 0.f);
            if (r < n) {
                float2 h = ((const float2*)H)[(size_t)r * 64 + half * 32 + q];
                v.x = fmaxf(sc[k] * h.x + sh[k], 0.f);
                v.y = fmaxf(sc[k + 1] * h.y + sh[k + 1], 0.f);
            }
            unsigned short h0, l0, h1, l1;
            bsplit(v.x, h0, l0);
            bsplit(v.y, h1, l1);
            unsigned boff = (unsigned)(row * 72 + q * 2) * 2;
            *(unsigned*)(smem + SM_AHI + boff) = pk(h0, h1);
            *(unsigned*)(smem + SM_ALO + boff) = pk(l0, l1);
        }
        if (half == 0) CP_WAIT0();
        __syncthreads();
        mma_half(sbase, warp, lane, half, c);
        __syncthreads();
    }

    float* buf = (float*)(smem + SM_BUF);
    frag_to_buf(buf, warp, lane, c);
    __syncthreads();

    {
        int t = tid & 127;
        int rbeg = (tid >> 7) * 64;
        float bias_t = ((const float*)(smem + SM_BIAS))[t];
        const int* gsm = (const int*)(smem + SM_G);
        int rmax = n - r0;
        if (rmax > 128) rmax = 128;
        int rend = rbeg + 64;
        if (rend > rmax) rend = rmax;
        int cur = -1;
        float rs = 0.f, rm = 0.f;
        for (int row = rbeg; row < rend; row++) {
            float o = fmaxf(buf[row * 132 + t] + bias_t, 0.f);
            if (writeH) out[(size_t)(r0 + row) * 128 + t] = o;
            int g = gsm[row];
            if (g != cur) {
                if (cur >= 0 && cur < GMAX) {
                    red_add_f(&psum[(size_t)cur * 128 + t], rs);
                    red_max_u32(&pmax[(size_t)cur * 128 + t], __float_as_uint(rm));
                }
                cur = g;
                rs = 0.f;
                rm = 0.f;
            }
            rs += o;
            rm = fmaxf(rm, o);
        }
        if (cur >= 0 && cur < GMAX) {
            red_add_f(&psum[(size_t)cur * 128 + t], rs);
            red_max_u32(&pmax[(size_t)cur * 128 + t], __float_as_uint(rm));
        }
    }
}

// ---------------- readout ----------------
__global__ __launch_bounds__(512) void readout_kernel(
    const float* __restrict__ W1, const float* __restrict__ b1,
    const float* __restrict__ W2, const float* __restrict__ b2,
    float* __restrict__ out, int Gn, int write_logits) {
    __shared__ float feats[8][512];
    __shared__ float red[512];
    int c = threadIdx.x;
    int g0 = blockIdx.x * 8;

#pragma unroll
    for (int i = 0; i < 8; i++) {
        int g = g0 + i;
        float v = 0.0f;
        if (g < Gn) {
            if (c < 128)      v = g_pa1[g * D + c];
            else if (c < 256) v = g_pa2[g * D + (c - 128)];
            else if (c < 384) v = __uint_as_float(g_pm1[g * D + (c - 256)]);
            else              v = __uint_as_float(g_pm2[g * D + (c - 384)]);
        }
        feats[i][c] = v;
    }
    __syncthreads();

    float acc[8];
#pragma unroll
    for (int i = 0; i < 8; i++) acc[i] = b1[c];

    for (int k = 0; k < 512; k++) {
        float w = W1[k * 512 + c];
#pragma unroll
        for (int i = 0; i < 8; i++) acc[i] += feats[i][k] * w;
    }

    float l2w = W2[c];
    for (int i = 0; i < 8; i++) {
        red[c] = fmaxf(acc[i], 0.0f) * l2w;
        __syncthreads();
        for (int s = 256; s > 0; s >>= 1) {
            if (c < s) red[c] += red[c + s];
            __syncthreads();
        }
        if (c == 0) {
            int g = g0 + i;
            if (g < Gn) {
                float logit = red[0] + b2[0];
                out[g] = 1.0f / (1.0f + expf(-logit));
                if (write_logits) out[Gn + g] = logit;
            }
        }
        __syncthreads();
    }
}

// ---------------- host ----------------
extern "C" void kernel_launch(void* const* d_in, const int* in_sizes, int n_in,
                              void* d_out, int out_size) {
    const float* x     = (const float*)d_in[0];
    const int*   ei    = (const int*)d_in[1];
    const int*   batch = (const int*)d_in[2];
    const float* c1_W1 = (const float*)d_in[3];
    const float* c1_b1 = (const float*)d_in[4];
    const float* c1_g  = (const float*)d_in[5];
    const float* c1_be = (const float*)d_in[6];
    const float* c1_W2 = (const float*)d_in[7];
    const float* c1_b2 = (const float*)d_in[8];
    const float* c2_W1 = (const float*)d_in[9];
    const float* c2_b1 = (const float*)d_in[10];
    const float* c2_g  = (const float*)d_in[11];
    const float* c2_be = (const float*)d_in[12];
    const float* c2_W2 = (const float*)d_in[13];
    const float* c2_b2 = (const float*)d_in[14];
    const float* lin1_W = (const float*)d_in[15];
    const float* lin1_b = (const float*)d_in[16];
    const float* lin2_W = (const float*)d_in[17];
    const float* lin2_b = (const float*)d_in[18];
    float* out = (float*)d_out;

    int n = in_sizes[0] / D;
    int E = in_sizes[1] / 2;
    if (E > EMAX) E = EMAX;
    int Gn, write_logits;
    if (out_size >= 2 * GMAX) { Gn = out_size / 2; write_logits = 1; }
    else                      { Gn = out_size;     write_logits = 0; }

    float *agg1, *agg2, *h, *h1, *pa1, *pa2, *sum, *sq;
    unsigned int *pm1, *pm2;
    unsigned short* wimg;
    int *head, *nxt;
    cudaGetSymbolAddress((void**)&agg1, g_agg1);
    cudaGetSymbolAddress((void**)&agg2, g_agg2);
    cudaGetSymbolAddress((void**)&h,    g_h);
    cudaGetSymbolAddress((void**)&h1,   g_h1);
    cudaGetSymbolAddress((void**)&pa1,  g_pa1);
    cudaGetSymbolAddress((void**)&pa2,  g_pa2);
    cudaGetSymbolAddress((void**)&pm1,  g_pm1);
    cudaGetSymbolAddress((void**)&pm2,  g_pm2);
    cudaGetSymbolAddress((void**)&sum,  g_sum);
    cudaGetSymbolAddress((void**)&sq,   g_sq);
    cudaGetSymbolAddress((void**)&wimg, g_wimg);
    cudaGetSymbolAddress((void**)&head, g_head);
    cudaGetSymbolAddress((void**)&nxt,  g_nxt);

    cudaFuncSetAttribute(gemm_stats, cudaFuncAttributeMaxDynamicSharedMemorySize, SM_TOTAL);
    cudaFuncSetAttribute(gemm_bnrelu, cudaFuncAttributeMaxDynamicSharedMemorySize, SM_TOTAL);

    int gemmBlocks = (n + 127) / 128;
    int gatherBlocks = (n * 16 + 255) / 256;
    int edgeBlocks = (E + 255) / 256;

    const unsigned short* w0 = wimg + 0 * 2 * 17408;
    const unsigned short* w1 = wimg + 1 * 2 * 17408;
    const unsigned short* w2 = wimg + 2 * 2 * 17408;
    const unsigned short* w3 = wimg + 3 * 2 * 17408;

    // 0-1: init (+weight prep) + edge list build
    init_kernel<<<516, 256>>>(pa1, pa2, pm1, pm2, head, n,
                              c1_W1, c1_W2, c2_W1, c2_W2);
    build_list<<<edgeBlocks, 256>>>(ei, head, nxt, E, n);
    // 2-4: conv1
    gather_kernel<<<gatherBlocks, 256>>>(x, ei, head, nxt, agg1, n);
    gemm_stats<<<gemmBlocks, 256, SM_TOTAL>>>(agg1, w0, c1_b1, h, sum, sq, n);
    gemm_bnrelu<<<gemmBlocks, 256, SM_TOTAL>>>(h, w1, c1_b2, h1, batch, pa1, pm1,
                                               sum, sq, c1_g, c1_be, n, 1);
    // 5-7: conv2
    gather_kernel<<<gatherBlocks, 256>>>(h1, ei, head, nxt, agg2, n);
    gemm_stats<<<gemmBlocks, 256, SM_TOTAL>>>(agg2, w2, c2_b1, h, sum + D, sq + D, n);
    gemm_bnrelu<<<gemmBlocks, 256, SM_TOTAL>>>(h, w3, c2_b2, (float*)0, batch, pa2, pm2,
                                               sum + D, sq + D, c2_g, c2_be, n, 0);
    // 8: readout
    readout_kernel<<<(Gn + 7) / 8, 512>>>(lin1_W, lin1_b, lin2_W, lin2_b,
                                          out, Gn, write_logits);
}